// round 13
// baseline (speedup 1.0000x reference)
#include <cuda_runtime.h>
#include <math.h>
#include <stdint.h>

// ---------------- problem constants ----------------
constexpr int D      = 4096;
constexpr int DW     = D / 2;          // 2048 bf16x2 words per row
constexpr int NTOT   = 2000;
constexpr int NL     = 500;
constexpr int NU     = 1500;
constexpr int WAY    = 100;
constexpr int NUW    = NU * WAY;      // 150000
constexpr int WAYD   = WAY * D;       // 409600
constexpr float LAMB   = 10.0f;
constexpr float ALPHAC = 0.2f;
constexpr int KSPL   = 4;              // gram k-splits
constexpr int EXPK_BLOCKS = (NUW + 255) / 256;   // 586
constexpr int USPL   = 376;            // epi u-split (pair-aligned)

// ---------------- device scratch ----------------
__device__ float g_X1[NTOT * D];
__device__ float g_Z[NTOT * D];
__device__ uint32_t g_ZuPack[NU * DW];     // bf16x2 (d-paired) unlabeled features
__device__ uint32_t g_musPack[WAY * DW];   // bf16x2 (d-paired) class means
__device__ uint32_t g_PuPack[(NU / 2) * WAY]; // bf16x2 (u-paired) transport plan
__device__ float g_zn2[NTOT];
__device__ float g_meanL[D], g_meanU[D];
__device__ float g_Sl[WAYD];
__device__ float g_mus[WAYD];
__device__ float g_mn2[WAY];
__device__ float g_Cpart[KSPL * NUW];
__device__ float g_Kmat[NUW];
__device__ float g_Kpart[600];
__device__ float g_Pu[NUW];
__device__ float g_colPpart[16 * 128];
__device__ float g_Epart[4 * WAYD];
__device__ int   g_accN;

// ---------------- helpers ----------------
__device__ __forceinline__ float blockReduceSum(float v) {
    static __shared__ float sh[32];
    __syncthreads();
    int lane = threadIdx.x & 31, wid = threadIdx.x >> 5;
    #pragma unroll
    for (int off = 16; off; off >>= 1) v += __shfl_xor_sync(0xffffffffu, v, off);
    if (lane == 0) sh[wid] = v;
    __syncthreads();
    int nw = (blockDim.x + 31) >> 5;
    float r = 0.0f;
    if (wid == 0) {
        r = (lane < nw) ? sh[lane] : 0.0f;
        #pragma unroll
        for (int off = 16; off; off >>= 1) r += __shfl_xor_sync(0xffffffffu, r, off);
        if (lane == 0) sh[0] = r;
    }
    __syncthreads();
    return sh[0];
}

// pack two floats into bf16x2 (lo in low half, hi in high half)
__device__ __forceinline__ uint32_t bfpack(float lo, float hi) {
    uint32_t r;
    asm("cvt.rn.bf16x2.f32 %0, %1, %2;" : "=r"(r) : "f"(hi), "f"(lo));
    return r;
}

__device__ __forceinline__ uint32_t prmt(uint32_t a, uint32_t b, uint32_t sel) {
    uint32_t r;
    asm("prmt.b32 %0, %1, %2, %3;" : "=r"(r) : "r"(a), "r"(b), "r"(sel));
    return r;
}

__device__ __forceinline__ void mma_bf16(float c[4], uint32_t a0, uint32_t a1,
                                         uint32_t a2, uint32_t a3,
                                         uint32_t b0, uint32_t b1) {
    asm volatile(
        "mma.sync.aligned.m16n8k16.row.col.f32.bf16.bf16.f32 "
        "{%0,%1,%2,%3}, {%4,%5,%6,%7}, {%8,%9}, {%0,%1,%2,%3};\n"
        : "+f"(c[0]), "+f"(c[1]), "+f"(c[2]), "+f"(c[3])
        : "r"(a0), "r"(a1), "r"(a2), "r"(a3), "r"(b0), "r"(b1));
}

__device__ __forceinline__ float dsmem_ld(uint32_t local_addr, uint32_t rank) {
    float v;
    asm volatile(
        "{\n\t"
        ".reg .b32 ra;\n\t"
        "mapa.shared::cluster.u32 ra, %1, %2;\n\t"
        "ld.shared::cluster.f32 %0, [ra];\n\t"
        "}"
        : "=f"(v) : "r"(local_addr), "r"(rank));
    return v;
}

// arrive (release, cluster scope) on rank's mbarrier at same smem offset
__device__ __forceinline__ void mbar_arrive_rank(uint32_t local_addr, uint32_t rank) {
    asm volatile(
        "{\n\t"
        ".reg .b32 ra;\n\t"
        "mapa.shared::cluster.u32 ra, %0, %1;\n\t"
        "mbarrier.arrive.release.cluster.shared::cluster.b64 _, [ra];\n\t"
        "}"
        :: "r"(local_addr), "r"(rank) : "memory");
}

#define MBAR_INIT(addr, cnt) \
    asm volatile("mbarrier.init.shared.b64 [%0], %1;" :: "r"(addr), "r"(cnt) : "memory")

#define MBAR_WAIT_CLUSTER(addr, ph) do { \
    uint32_t _done; \
    asm volatile("{\n\t.reg .pred p;\n\t" \
        "mbarrier.try_wait.parity.acquire.cluster.shared::cta.b64 p, [%1], %2;\n\t" \
        "selp.b32 %0, 1, 0, p;\n\t}" : "=r"(_done) : "r"(addr), "r"(ph) : "memory"); \
    if (!_done) { \
        asm volatile("{\n\t.reg .pred P1;\n\t" \
            "WL_%=:\n\t" \
            "mbarrier.try_wait.parity.acquire.cluster.shared::cta.b64 P1, [%0], %1, 0x989680;\n\t" \
            "@P1 bra.uni WD_%=;\n\t" \
            "bra.uni WL_%=;\n\t" \
            "WD_%=:\n\t}" \
            :: "r"(addr), "r"(ph) : "memory"); \
    } \
} while (0)

#define CLUSTER_SYNC() do { \
    asm volatile("barrier.cluster.arrive.aligned;" ::: "memory"); \
    asm volatile("barrier.cluster.wait.aligned;" ::: "memory"); \
} while (0)

// ---------------- preprocessing ----------------
__global__ void k_pre1(const float* __restrict__ X) {
    int row = blockIdx.x, t = threadIdx.x;
    __shared__ float buf[D];
    float ss = 0.0f;
    for (int d = t; d < D; d += blockDim.x) {
        float v = sqrtf(X[(size_t)row * D + d] + 1e-6f);
        buf[d] = v; ss += v * v;
    }
    ss = blockReduceSum(ss);
    float inv = 1.0f / fmaxf(sqrtf(ss), 1e-12f);
    for (int d = t; d < D; d += blockDim.x) g_X1[(size_t)row * D + d] = buf[d] * inv;
}

__global__ void k_colmeans() {
    int lane = threadIdx.x & 63;
    int part = threadIdx.x >> 6;         // 0..3
    int d = blockIdx.x * 64 + lane;
    __shared__ float sh[4][64];
    float sL = 0.0f;
    for (int i = part * 125; i < (part + 1) * 125; i++) sL += g_X1[(size_t)i * D + d];
    sh[part][lane] = sL;
    __syncthreads();
    if (part == 0)
        g_meanL[d] = (sh[0][lane] + sh[1][lane] + sh[2][lane] + sh[3][lane]) * (1.0f / NL);
    __syncthreads();
    float sU = 0.0f;
    for (int i = NL + part * 375; i < NL + (part + 1) * 375; i++) sU += g_X1[(size_t)i * D + d];
    sh[part][lane] = sU;
    __syncthreads();
    if (part == 0)
        g_meanU[d] = (sh[0][lane] + sh[1][lane] + sh[2][lane] + sh[3][lane]) * (1.0f / NU);
}

__global__ void k_pre2() {
    int row = blockIdx.x, t = threadIdx.x;
    __shared__ float buf[D];
    const float* mean = (row < NL) ? g_meanL : g_meanU;
    float ss = 0.0f;
    for (int d = t; d < D; d += 256) {
        float v = g_X1[(size_t)row * D + d] - mean[d];
        buf[d] = v; ss += v * v;
    }
    ss = blockReduceSum(ss);
    float inv = 1.0f / fmaxf(sqrtf(ss), 1e-12f);
    if (t == 0) g_zn2[row] = ss * inv * inv;
    for (int i = t; i < DW; i += 256) {
        float lo = buf[2 * i] * inv, hi = buf[2 * i + 1] * inv;
        ((float2*)g_Z)[(size_t)row * DW + i] = make_float2(lo, hi);
        if (row >= NL) g_ZuPack[(size_t)(row - NL) * DW + i] = bfpack(lo, hi);
    }
}

// one block (512 thr) per class: Sl, mus0, musPack, mn2
__global__ void __launch_bounds__(512) k_Sl() {
    int c = blockIdx.x, t = threadIdx.x;
    float ss = 0.0f;
    #pragma unroll
    for (int q = 0; q < 4; q++) {
        int i = t + 512 * q;           // word index 0..2047
        int d0 = 2 * i;
        float s0 = 0.0f, s1 = 0.0f;
        #pragma unroll
        for (int k = 0; k < 5; k++) {
            float2 z = ((const float2*)g_Z)[(size_t)(k * WAY + c) * DW + i];
            s0 += z.x; s1 += z.y;
        }
        g_Sl[c * D + d0] = s0; g_Sl[c * D + d0 + 1] = s1;
        float m0 = s0 * 0.2f, m1 = s1 * 0.2f;
        g_mus[c * D + d0] = m0; g_mus[c * D + d0 + 1] = m1;
        g_musPack[c * DW + i] = bfpack(m0, m1);
        ss += m0 * m0 + m1 * m1;
    }
    ss = blockReduceSum(ss);
    if (t == 0) g_mn2[c] = ss;
}

// ===== bf16 tensor-core gram from pre-packed operands (4 k-splits of 1024)
__global__ void __launch_bounds__(256) k_gram() {
    const int r0 = blockIdx.x * 64;
    const int k0 = blockIdx.y * 1024;
    const int t  = threadIdx.x;
    const int w  = t >> 5, lane = t & 31;
    const int gid = lane >> 2, tig = lane & 3;
    const int m0w = (w >> 1) * 16;
    const int n0w = (w & 1) * 56;

    __shared__ uint32_t As[64][36];   // [m][k-pair] bf16x2 (stride 36: conflict-free)
    __shared__ uint32_t Bs[112][36];  // [n][k-pair]

    float c[7][4];
    #pragma unroll
    for (int i = 0; i < 7; i++)
        #pragma unroll
        for (int jj = 0; jj < 4; jj++) c[i][jj] = 0.0f;

    const int arow = t >> 2;          // 0..63
    const int af4  = t & 3;

    for (int kt = 0; kt < 1024; kt += 64) {
        const int kw = (k0 + kt) >> 1;      // word base
        #pragma unroll
        for (int i = 0; i < 4; i++) {
            int f4 = af4 + 4 * i;
            uint2 v = make_uint2(0u, 0u);
            if (r0 + arow < NU) v = *(const uint2*)&g_ZuPack[(size_t)(r0 + arow) * DW + kw + f4 * 2];
            As[arow][f4 * 2]     = v.x;
            As[arow][f4 * 2 + 1] = v.y;
        }
        #pragma unroll
        for (int i = 0; i < 7; i++) {
            int idx = t + 256 * i;
            int row = idx >> 4, f4 = idx & 15;
            uint2 v = make_uint2(0u, 0u);
            if (row < WAY) v = *(const uint2*)&g_musPack[(size_t)row * DW + kw + f4 * 2];
            Bs[row][f4 * 2]     = v.x;
            Bs[row][f4 * 2 + 1] = v.y;
        }
        __syncthreads();
        #pragma unroll
        for (int ks = 0; ks < 4; ks++) {
            const int kp = ks * 8;
            uint32_t a0 = As[m0w + gid][kp + tig];
            uint32_t a1 = As[m0w + gid + 8][kp + tig];
            uint32_t a2 = As[m0w + gid][kp + tig + 4];
            uint32_t a3 = As[m0w + gid + 8][kp + tig + 4];
            #pragma unroll
            for (int nt = 0; nt < 7; nt++) {
                uint32_t b0 = Bs[n0w + nt * 8 + gid][kp + tig];
                uint32_t b1 = Bs[n0w + nt * 8 + gid][kp + tig + 4];
                mma_bf16(c[nt], a0, a1, a2, a3, b0, b1);
            }
        }
        __syncthreads();
    }
    float* out = g_Cpart + (size_t)blockIdx.y * NUW;
    #pragma unroll
    for (int nt = 0; nt < 7; nt++) {
        int j0 = n0w + nt * 8 + tig * 2;
        int gr0 = r0 + m0w + gid;
        #pragma unroll
        for (int h = 0; h < 2; h++) {
            int gr = gr0 + 8 * h;
            if (gr < NU) {
                if (j0 < WAY)     out[gr * WAY + j0]     = c[nt][2 * h];
                if (j0 + 1 < WAY) out[gr * WAY + j0 + 1] = c[nt][2 * h + 1];
            }
        }
    }
}

// K = exp(-lam*dist); wide grid (memory phase stays chip-wide — R5/R10 lesson)
__global__ void k_expK() {
    int idx = blockIdx.x * blockDim.x + threadIdx.x;
    float kv = 0.0f;
    if (idx < NUW) {
        int i = idx / WAY, j = idx - i * WAY;
        float c = 0.0f;
        #pragma unroll
        for (int s = 0; s < KSPL; s++) c += g_Cpart[s * NUW + idx];
        float d2 = g_zn2[NL + i] + g_mn2[j] - 2.0f * c;
        float dist = sqrtf(fmaxf(d2, 1e-12f));
        kv = expf(-LAMB * dist);
        g_Kmat[idx] = kv;
    }
    float bs = blockReduceSum(kv);
    if (threadIdx.x == 0) g_Kpart[blockIdx.x] = bs;
}

// ---------------- cluster-based persistent sinkhorn (NB CTAs x 512) ----------------
// mbarrier all-to-all barrier replaces cluster.sync in the hot loop.
template <int NB, int RW>
__global__ void __launch_bounds__(512, 1) k_sink(int writeF32) {
    const int t = threadIdx.x, w = t >> 5, lane = t & 31;
    const int blk = blockIdx.x;           // == cluster rank (single cluster)
    const int gw  = blk * 16 + w;
    const int rbase = gw * RW;
    __shared__ float scolW[16][128];
    __shared__ float sWerr[16];
    __shared__ float colsumBuf[2][128];
    __shared__ float errBuf[2];
    __shared__ float sbcast[128];
    __shared__ float sErrSh;
    __shared__ __align__(8) uint64_t smbar[2];

    if (t == 0) { MBAR_INIT((uint32_t)__cvta_generic_to_shared(&smbar[0]), NB);
                  MBAR_INIT((uint32_t)__cvta_generic_to_shared(&smbar[1]), NB); }

    // Ksum from expK partials (identical fixed-order computation in every block)
    float ks = 0.0f;
    for (int i = t; i < EXPK_BLOCKS; i += 512) ks += __ldcg(&g_Kpart[i]);
    ks = blockReduceSum(ks);
    const float invKs = 1.0f / ks;

    float Kr[RW][4], a[RW], prev[RW], b[4];
    bool rv[RW], cv[4];
    int cols[4];
    #pragma unroll
    for (int c = 0; c < 4; c++) {
        int j = lane + 32 * c;
        cols[c] = j; cv[c] = (j < WAY); b[c] = cv[c] ? 1.0f : 0.0f;
    }
    #pragma unroll
    for (int k = 0; k < RW; k++) {
        int r = rbase + k;
        rv[k] = (r < NU); a[k] = 1.0f; prev[k] = 0.0f;
        #pragma unroll
        for (int c = 0; c < 4; c++)
            Kr[k][c] = (rv[k] && cv[c]) ? g_Kmat[r * WAY + cols[c]] * invKs : 0.0f;
    }

    // make mbarrier inits visible cluster-wide before any remote arrive
    CLUSTER_SYNC();

    const uint32_t colBufAddr0 = (uint32_t)__cvta_generic_to_shared(&colsumBuf[0][0]);
    const uint32_t colBufAddr1 = (uint32_t)__cvta_generic_to_shared(&colsumBuf[1][0]);
    const uint32_t errAddr0    = (uint32_t)__cvta_generic_to_shared(&errBuf[0]);
    const uint32_t errAddr1    = (uint32_t)__cvta_generic_to_shared(&errBuf[1]);
    const uint32_t mbarAddr0   = (uint32_t)__cvta_generic_to_shared(&smbar[0]);

    float rowsum[RW];
    for (int it = 0; it < 1000; ++it) {
        const int p = it & 1;
        const int ph = (it >> 1) & 1;       // parity of slot p's use
        float werr = 0.0f;
        {
            float anew[RW];
            #pragma unroll
            for (int k = 0; k < RW; k++) {
                float s = 0.0f;
                #pragma unroll
                for (int c = 0; c < 4; c++) s = fmaf(Kr[k][c], b[c], s);
                #pragma unroll
                for (int off = 16; off; off >>= 1) s += __shfl_xor_sync(0xffffffffu, s, off);
                rowsum[k] = a[k] * s;
                anew[k] = rv[k] ? a[k] / rowsum[k] : 0.0f;
                if (rv[k]) werr = fmaxf(werr, fabsf(prev[k] - rowsum[k]));
            }
            #pragma unroll
            for (int c = 0; c < 4; c++) {
                float s = 0.0f;
                #pragma unroll
                for (int k = 0; k < RW; k++) s = fmaf(Kr[k][c], anew[k], s);
                scolW[w][cols[c]] = cv[c] ? s : 0.0f;
            }
        }   // anew dead before the barrier (register pressure)
        if (lane == 0) sWerr[w] = werr;
        __syncthreads();
        if (t < 128) {
            float s = scolW[0][t];
            #pragma unroll
            for (int ww = 1; ww < 16; ww++) s += scolW[ww][t];
            colsumBuf[p][t] = s;
        }
        if (t == 128) {
            float e = sWerr[0];
            #pragma unroll
            for (int ww = 1; ww < 16; ww++) e = fmaxf(e, sWerr[ww]);
            errBuf[p] = e;
        }
        __syncthreads();
        if (t == 0) {
            uint32_t lbar = mbarAddr0 + p * 8;
            #pragma unroll
            for (int bb = 0; bb < NB; bb++) mbar_arrive_rank(lbar, (uint32_t)bb);
        }
        MBAR_WAIT_CLUSTER(mbarAddr0 + p * 8, ph);
        if (t < 128) {
            uint32_t addr = (p ? colBufAddr1 : colBufAddr0) + t * 4;
            float s = 0.0f;
            #pragma unroll
            for (int bb = 0; bb < NB; bb++) s += dsmem_ld(addr, (uint32_t)bb);
            sbcast[t] = s;
        }
        if (t == 128) {
            uint32_t addr = p ? errAddr1 : errAddr0;
            float e = 0.0f;
            #pragma unroll
            for (int bb = 0; bb < NB; bb++) e = fmaxf(e, dsmem_ld(addr, (uint32_t)bb));
            sErrSh = e;
        }
        __syncthreads();
        if (sErrSh <= 1e-6f) break;     // a,b stay pre-update: exact reference semantics
        #pragma unroll
        for (int k = 0; k < RW; k++) {
            if (rv[k]) { a[k] = a[k] / rowsum[k]; prev[k] = rowsum[k]; }
        }
        #pragma unroll
        for (int c = 0; c < 4; c++) if (cv[c]) b[c] = 15.0f / sbcast[cols[c]];
        __syncthreads();                // protect sbcast/scolW before next-iter writes
    }

    // epilogue: write packed Pu pairs (+ f32 on final epoch) + colP partials
    float colacc[4] = {0.f, 0.f, 0.f, 0.f};
    #pragma unroll
    for (int k = 0; k < RW; k += 2) {   // rv[k]==rv[k+1] (NU even, rbase even)
        int r = rbase + k;
        if (!rv[k]) continue;
        #pragma unroll
        for (int c = 0; c < 4; c++) {
            if (cv[c]) {
                float p0 = a[k] * Kr[k][c] * b[c];
                float p1 = a[k + 1] * Kr[k + 1][c] * b[c];
                g_PuPack[(r >> 1) * WAY + cols[c]] = bfpack(p0, p1);
                if (writeF32) {
                    g_Pu[r * WAY + cols[c]]       = p0;
                    g_Pu[(r + 1) * WAY + cols[c]] = p1;
                }
                colacc[c] += p0 + p1;
            }
        }
    }
    __syncthreads();
    #pragma unroll
    for (int c = 0; c < 4; c++) scolW[w][cols[c]] = cv[c] ? colacc[c] : 0.0f;
    __syncthreads();
    if (t < 128) {
        float s = scolW[0][t];
        #pragma unroll
        for (int ww = 1; ww < 16; ww++) s += scolW[ww][t];
        __stcg(&g_colPpart[blk * 128 + t], s);
    }
    CLUSTER_SYNC();                     // no CTA exits while peers may still read its smem
}

// ===== bf16 tensor-core epilogue GEMM from pre-packed operands
__global__ void __launch_bounds__(256) k_epi() {
    const int n0 = blockIdx.x * 64;
    const int u0 = blockIdx.y * USPL;
    const int t  = threadIdx.x;
    const int w  = t >> 5, lane = t & 31;
    const int gid = lane >> 2, tig = lane & 3;
    const int m0w = w * 16;

    __shared__ uint32_t As[128][20];  // [class][u-pair] bf16x2
    __shared__ uint32_t Bs[64][20];   // [dim][u-pair]

    float c[8][4];
    #pragma unroll
    for (int i = 0; i < 8; i++)
        #pragma unroll
        for (int jj = 0; jj < 4; jj++) c[i][jj] = 0.0f;

    const int am  = t & 127;
    const int ah  = t >> 7;
    const int bup = t >> 4;
    const int bnn = (t & 15) * 4;

    for (int kt = 0; kt < 12; kt++) {
        const int ub = kt * 32;
        const int pairBase = (u0 >> 1) + (ub >> 1);
        #pragma unroll
        for (int i = 0; i < 8; i++) {
            int kp = ah * 8 + i;
            int ul = ub + kp * 2;
            uint32_t v = 0u;
            if (am < WAY && ul < USPL && u0 + ul < NU)
                v = g_PuPack[(pairBase + kp) * WAY + am];
            As[am][kp] = v;
        }
        {
            int ul = ub + bup * 2;
            uint2 w0 = make_uint2(0u, 0u), w1 = make_uint2(0u, 0u);
            if (ul < USPL && u0 + ul < NU) {
                w0 = *(const uint2*)&g_ZuPack[(size_t)(u0 + ul) * DW + ((n0 + bnn) >> 1)];
                w1 = *(const uint2*)&g_ZuPack[(size_t)(u0 + ul + 1) * DW + ((n0 + bnn) >> 1)];
            }
            Bs[bnn + 0][bup] = prmt(w0.x, w1.x, 0x5410);
            Bs[bnn + 1][bup] = prmt(w0.x, w1.x, 0x7632);
            Bs[bnn + 2][bup] = prmt(w0.y, w1.y, 0x5410);
            Bs[bnn + 3][bup] = prmt(w0.y, w1.y, 0x7632);
        }
        __syncthreads();
        #pragma unroll
        for (int ks = 0; ks < 2; ks++) {
            const int kp = ks * 8;
            uint32_t a0 = As[m0w + gid][kp + tig];
            uint32_t a1 = As[m0w + gid + 8][kp + tig];
            uint32_t a2 = As[m0w + gid][kp + tig + 4];
            uint32_t a3 = As[m0w + gid + 8][kp + tig + 4];
            #pragma unroll
            for (int nt = 0; nt < 8; nt++) {
                uint32_t b0 = Bs[nt * 8 + gid][kp + tig];
                uint32_t b1 = Bs[nt * 8 + gid][kp + tig + 4];
                mma_bf16(c[nt], a0, a1, a2, a3, b0, b1);
            }
        }
        __syncthreads();
    }
    float* outp = g_Epart + (size_t)blockIdx.y * WAYD;
    #pragma unroll
    for (int nt = 0; nt < 8; nt++) {
        int dcol = n0 + nt * 8 + tig * 2;
        #pragma unroll
        for (int h = 0; h < 2; h++) {
            int j = m0w + gid + 8 * h;
            if (j < WAY) {
                outp[(size_t)j * D + dcol]     = c[nt][2 * h];
                outp[(size_t)j * D + dcol + 1] = c[nt][2 * h + 1];
            }
        }
    }
}

// one block per class: mus update + musPack + mn2 for next epoch
__global__ void __launch_bounds__(512) k_update(int nb) {
    const int j = blockIdx.x, t = threadIdx.x;
    __shared__ float sden;
    if (t == 0) {
        float s = 0.0f;
        for (int bb = 0; bb < nb; bb++) s += g_colPpart[bb * 128 + j];
        sden = 5.0f + s;
    }
    __syncthreads();
    const float invden = 1.0f / sden;
    float ss = 0.0f;
    #pragma unroll
    for (int q = 0; q < 4; q++) {
        int i = t + 512 * q;           // word index 0..2047
        int idx = j * D + 2 * i;
        float E0 = 0.0f, E1 = 0.0f;
        #pragma unroll
        for (int s = 0; s < 4; s++) {
            E0 += g_Epart[s * WAYD + idx];
            E1 += g_Epart[s * WAYD + idx + 1];
        }
        float em0 = (g_Sl[idx] + E0) * invden;
        float em1 = (g_Sl[idx + 1] + E1) * invden;
        float m0 = g_mus[idx],     m1 = g_mus[idx + 1];
        m0 = m0 + ALPHAC * (em0 - m0);
        m1 = m1 + ALPHAC * (em1 - m1);
        g_mus[idx] = m0; g_mus[idx + 1] = m1;
        g_musPack[j * DW + i] = bfpack(m0, m1);
        ss += m0 * m0 + m1 * m1;
    }
    ss = blockReduceSum(ss);
    if (t == 0) g_mn2[j] = ss;
}

// ---------------- output ----------------
__global__ void k_out(float* __restrict__ out) {
    int idx = blockIdx.x * blockDim.x + threadIdx.x;
    if (idx == 0) g_accN = 0;
    if (idx < NUW) out[idx] = logf(g_Pu[idx] + 1e-5f);
}

__global__ void k_acc(const int* __restrict__ labels) {
    int i = blockIdx.x * blockDim.x + threadIdx.x;
    if (i >= NU) return;
    const float* row = g_Pu + i * WAY;
    float best = row[0]; int bj = 0;
    for (int j = 1; j < WAY; j++) {
        float v = row[j];
        if (v > best) { best = v; bj = j; }
    }
    if (bj == labels[NL + i]) atomicAdd(&g_accN, 1);
}

__global__ void k_accw(float* __restrict__ out) {
    out[NUW] = (float)g_accN * (1.0f / NU);
}

// ---------------- launch ----------------
extern "C" void kernel_launch(void* const* d_in, const int* in_sizes, int n_in,
                              void* d_out, int out_size) {
    const float* X = (const float*)d_in[0];
    const int* labels = (const int*)d_in[1];
    float* out = (float*)d_out;

    // probe 16-CTA nonportable cluster support (host API, deterministic per machine)
    int nb = 8;
    {
        cudaFuncSetAttribute((const void*)k_sink<16, 6>,
                             cudaFuncAttributeNonPortableClusterSizeAllowed, 1);
        cudaLaunchConfig_t pc = {};
        pc.gridDim = dim3(16, 1, 1);
        pc.blockDim = dim3(512, 1, 1);
        int cs = 0;
        cudaError_t err = cudaOccupancyMaxPotentialClusterSize(
            &cs, (const void*)k_sink<16, 6>, &pc);
        if (err == cudaSuccess && cs >= 16) nb = 16;
        else cudaGetLastError();
    }

    k_pre1<<<NTOT, 256>>>(X);
    k_colmeans<<<D / 64, 256>>>();
    k_pre2<<<NTOT, 256>>>();
    k_Sl<<<WAY, 512>>>();

    cudaLaunchConfig_t cfg = {};
    cudaLaunchAttribute attrs[1];
    attrs[0].id = cudaLaunchAttributeClusterDimension;
    attrs[0].val.clusterDim.x = nb;
    attrs[0].val.clusterDim.y = 1;
    attrs[0].val.clusterDim.z = 1;
    cfg.gridDim = dim3(nb, 1, 1);
    cfg.blockDim = dim3(512, 1, 1);
    cfg.attrs = attrs;
    cfg.numAttrs = 1;

    for (int e = 0; e < 21; e++) {
        k_gram<<<dim3(24, KSPL), 256>>>();
        k_expK<<<EXPK_BLOCKS, 256>>>();
        int wf = (e == 20) ? 1 : 0;
        if (nb == 16) cudaLaunchKernelEx(&cfg, k_sink<16, 6>, wf);
        else          cudaLaunchKernelEx(&cfg, k_sink<8, 12>, wf);
        if (e < 20) {
            k_epi<<<dim3(64, 4), 256>>>();
            k_update<<<WAY, 512>>>(nb);
        }
    }
    k_out<<<(NUW + 255) / 256, 256>>>(out);
    k_acc<<<(NU + 255) / 256, 256>>>(labels);
    if (out_size > NUW) k_accw<<<1, 1>>>(out);
}

// round 14
// speedup vs baseline: 1.1209x; 1.1209x over previous
#include <cuda_runtime.h>
#include <math.h>
#include <stdint.h>

// ---------------- problem constants ----------------
constexpr int D      = 4096;
constexpr int DW     = D / 2;          // 2048 bf16x2 words per row
constexpr int NTOT   = 2000;
constexpr int NL     = 500;
constexpr int NU     = 1500;
constexpr int WAY    = 100;
constexpr int NUW    = NU * WAY;      // 150000
constexpr int WAYD   = WAY * D;       // 409600
constexpr float LAMB   = 10.0f;
constexpr float ALPHAC = 0.2f;
constexpr int KSPL   = 4;              // gram k-splits
constexpr int EXPK_BLOCKS = (NUW + 255) / 256;   // 586
constexpr int USPL   = 376;            // epi u-split (pair-aligned)

// ---------------- device scratch ----------------
__device__ float g_X1[NTOT * D];
__device__ float g_Z[NTOT * D];
__device__ uint32_t g_ZuPack[NU * DW];     // bf16x2 (d-paired) unlabeled features
__device__ uint32_t g_musPack[WAY * DW];   // bf16x2 (d-paired) class means
__device__ uint32_t g_PuPack[(NU / 2) * WAY]; // bf16x2 (u-paired) transport plan
__device__ float g_zn2[NTOT];
__device__ float g_meanL[D], g_meanU[D];
__device__ float g_Sl[WAYD];
__device__ float g_mus[WAYD];
__device__ float g_mn2[WAY];
__device__ float g_Cpart[KSPL * NUW];
__device__ float g_Kmat[NUW];
__device__ float g_Kpart[600];
__device__ float g_Pu[NUW];
__device__ float g_colPpart[16 * 128];
__device__ float g_Epart[4 * WAYD];
__device__ int   g_accN;

// ---------------- helpers ----------------
__device__ __forceinline__ float blockReduceSum(float v) {
    static __shared__ float sh[32];
    __syncthreads();
    int lane = threadIdx.x & 31, wid = threadIdx.x >> 5;
    #pragma unroll
    for (int off = 16; off; off >>= 1) v += __shfl_xor_sync(0xffffffffu, v, off);
    if (lane == 0) sh[wid] = v;
    __syncthreads();
    int nw = (blockDim.x + 31) >> 5;
    float r = 0.0f;
    if (wid == 0) {
        r = (lane < nw) ? sh[lane] : 0.0f;
        #pragma unroll
        for (int off = 16; off; off >>= 1) r += __shfl_xor_sync(0xffffffffu, r, off);
        if (lane == 0) sh[0] = r;
    }
    __syncthreads();
    return sh[0];
}

// pack two floats into bf16x2 (lo in low half, hi in high half)
__device__ __forceinline__ uint32_t bfpack(float lo, float hi) {
    uint32_t r;
    asm("cvt.rn.bf16x2.f32 %0, %1, %2;" : "=r"(r) : "f"(hi), "f"(lo));
    return r;
}

__device__ __forceinline__ uint32_t prmt(uint32_t a, uint32_t b, uint32_t sel) {
    uint32_t r;
    asm("prmt.b32 %0, %1, %2, %3;" : "=r"(r) : "r"(a), "r"(b), "r"(sel));
    return r;
}

__device__ __forceinline__ void mma_bf16(float c[4], uint32_t a0, uint32_t a1,
                                         uint32_t a2, uint32_t a3,
                                         uint32_t b0, uint32_t b1) {
    asm volatile(
        "mma.sync.aligned.m16n8k16.row.col.f32.bf16.bf16.f32 "
        "{%0,%1,%2,%3}, {%4,%5,%6,%7}, {%8,%9}, {%0,%1,%2,%3};\n"
        : "+f"(c[0]), "+f"(c[1]), "+f"(c[2]), "+f"(c[3])
        : "r"(a0), "r"(a1), "r"(a2), "r"(a3), "r"(b0), "r"(b1));
}

__device__ __forceinline__ float dsmem_ld(uint32_t local_addr, uint32_t rank) {
    float v;
    asm volatile(
        "{\n\t"
        ".reg .b32 ra;\n\t"
        "mapa.shared::cluster.u32 ra, %1, %2;\n\t"
        "ld.shared::cluster.f32 %0, [ra];\n\t"
        "}"
        : "=f"(v) : "r"(local_addr), "r"(rank));
    return v;
}

#define CLUSTER_SYNC() do { \
    asm volatile("barrier.cluster.arrive.aligned;" ::: "memory"); \
    asm volatile("barrier.cluster.wait.aligned;" ::: "memory"); \
} while (0)

// ---------------- preprocessing ----------------
__global__ void k_pre1(const float* __restrict__ X) {
    int row = blockIdx.x, t = threadIdx.x;
    __shared__ float buf[D];
    float ss = 0.0f;
    for (int d = t; d < D; d += blockDim.x) {
        float v = sqrtf(X[(size_t)row * D + d] + 1e-6f);
        buf[d] = v; ss += v * v;
    }
    ss = blockReduceSum(ss);
    float inv = 1.0f / fmaxf(sqrtf(ss), 1e-12f);
    for (int d = t; d < D; d += blockDim.x) g_X1[(size_t)row * D + d] = buf[d] * inv;
}

__global__ void k_colmeans() {
    int lane = threadIdx.x & 63;
    int part = threadIdx.x >> 6;         // 0..3
    int d = blockIdx.x * 64 + lane;
    __shared__ float sh[4][64];
    float sL = 0.0f;
    for (int i = part * 125; i < (part + 1) * 125; i++) sL += g_X1[(size_t)i * D + d];
    sh[part][lane] = sL;
    __syncthreads();
    if (part == 0)
        g_meanL[d] = (sh[0][lane] + sh[1][lane] + sh[2][lane] + sh[3][lane]) * (1.0f / NL);
    __syncthreads();
    float sU = 0.0f;
    for (int i = NL + part * 375; i < NL + (part + 1) * 375; i++) sU += g_X1[(size_t)i * D + d];
    sh[part][lane] = sU;
    __syncthreads();
    if (part == 0)
        g_meanU[d] = (sh[0][lane] + sh[1][lane] + sh[2][lane] + sh[3][lane]) * (1.0f / NU);
}

__global__ void k_pre2() {
    int row = blockIdx.x, t = threadIdx.x;
    __shared__ float buf[D];
    const float* mean = (row < NL) ? g_meanL : g_meanU;
    float ss = 0.0f;
    for (int d = t; d < D; d += 256) {
        float v = g_X1[(size_t)row * D + d] - mean[d];
        buf[d] = v; ss += v * v;
    }
    ss = blockReduceSum(ss);
    float inv = 1.0f / fmaxf(sqrtf(ss), 1e-12f);
    if (t == 0) g_zn2[row] = ss * inv * inv;
    for (int i = t; i < DW; i += 256) {
        float lo = buf[2 * i] * inv, hi = buf[2 * i + 1] * inv;
        ((float2*)g_Z)[(size_t)row * DW + i] = make_float2(lo, hi);
        if (row >= NL) g_ZuPack[(size_t)(row - NL) * DW + i] = bfpack(lo, hi);
    }
}

// one block (512 thr) per class: Sl, mus0, musPack, mn2
__global__ void __launch_bounds__(512) k_Sl() {
    int c = blockIdx.x, t = threadIdx.x;
    float ss = 0.0f;
    #pragma unroll
    for (int q = 0; q < 4; q++) {
        int i = t + 512 * q;           // word index 0..2047
        int d0 = 2 * i;
        float s0 = 0.0f, s1 = 0.0f;
        #pragma unroll
        for (int k = 0; k < 5; k++) {
            float2 z = ((const float2*)g_Z)[(size_t)(k * WAY + c) * DW + i];
            s0 += z.x; s1 += z.y;
        }
        g_Sl[c * D + d0] = s0; g_Sl[c * D + d0 + 1] = s1;
        float m0 = s0 * 0.2f, m1 = s1 * 0.2f;
        g_mus[c * D + d0] = m0; g_mus[c * D + d0 + 1] = m1;
        g_musPack[c * DW + i] = bfpack(m0, m1);
        ss += m0 * m0 + m1 * m1;
    }
    ss = blockReduceSum(ss);
    if (t == 0) g_mn2[c] = ss;
}

// ===== bf16 tensor-core gram from pre-packed operands (4 k-splits of 1024)
__global__ void __launch_bounds__(256) k_gram() {
    const int r0 = blockIdx.x * 64;
    const int k0 = blockIdx.y * 1024;
    const int t  = threadIdx.x;
    const int w  = t >> 5, lane = t & 31;
    const int gid = lane >> 2, tig = lane & 3;
    const int m0w = (w >> 1) * 16;
    const int n0w = (w & 1) * 56;

    __shared__ uint32_t As[64][36];   // [m][k-pair] bf16x2 (stride 36: conflict-free)
    __shared__ uint32_t Bs[112][36];  // [n][k-pair]

    float c[7][4];
    #pragma unroll
    for (int i = 0; i < 7; i++)
        #pragma unroll
        for (int jj = 0; jj < 4; jj++) c[i][jj] = 0.0f;

    const int arow = t >> 2;          // 0..63
    const int af4  = t & 3;

    for (int kt = 0; kt < 1024; kt += 64) {
        const int kw = (k0 + kt) >> 1;      // word base
        #pragma unroll
        for (int i = 0; i < 4; i++) {
            int f4 = af4 + 4 * i;
            uint2 v = make_uint2(0u, 0u);
            if (r0 + arow < NU) v = *(const uint2*)&g_ZuPack[(size_t)(r0 + arow) * DW + kw + f4 * 2];
            As[arow][f4 * 2]     = v.x;
            As[arow][f4 * 2 + 1] = v.y;
        }
        #pragma unroll
        for (int i = 0; i < 7; i++) {
            int idx = t + 256 * i;
            int row = idx >> 4, f4 = idx & 15;
            uint2 v = make_uint2(0u, 0u);
            if (row < WAY) v = *(const uint2*)&g_musPack[(size_t)row * DW + kw + f4 * 2];
            Bs[row][f4 * 2]     = v.x;
            Bs[row][f4 * 2 + 1] = v.y;
        }
        __syncthreads();
        #pragma unroll
        for (int ks = 0; ks < 4; ks++) {
            const int kp = ks * 8;
            uint32_t a0 = As[m0w + gid][kp + tig];
            uint32_t a1 = As[m0w + gid + 8][kp + tig];
            uint32_t a2 = As[m0w + gid][kp + tig + 4];
            uint32_t a3 = As[m0w + gid + 8][kp + tig + 4];
            #pragma unroll
            for (int nt = 0; nt < 7; nt++) {
                uint32_t b0 = Bs[n0w + nt * 8 + gid][kp + tig];
                uint32_t b1 = Bs[n0w + nt * 8 + gid][kp + tig + 4];
                mma_bf16(c[nt], a0, a1, a2, a3, b0, b1);
            }
        }
        __syncthreads();
    }
    float* out = g_Cpart + (size_t)blockIdx.y * NUW;
    #pragma unroll
    for (int nt = 0; nt < 7; nt++) {
        int j0 = n0w + nt * 8 + tig * 2;
        int gr0 = r0 + m0w + gid;
        #pragma unroll
        for (int h = 0; h < 2; h++) {
            int gr = gr0 + 8 * h;
            if (gr < NU) {
                if (j0 < WAY)     out[gr * WAY + j0]     = c[nt][2 * h];
                if (j0 + 1 < WAY) out[gr * WAY + j0 + 1] = c[nt][2 * h + 1];
            }
        }
    }
}

// K = exp(-lam*dist); wide grid (memory phase stays chip-wide — R5/R10 lesson)
__global__ void k_expK() {
    int idx = blockIdx.x * blockDim.x + threadIdx.x;
    float kv = 0.0f;
    if (idx < NUW) {
        int i = idx / WAY, j = idx - i * WAY;
        float c = 0.0f;
        #pragma unroll
        for (int s = 0; s < KSPL; s++) c += g_Cpart[s * NUW + idx];
        float d2 = g_zn2[NL + i] + g_mn2[j] - 2.0f * c;
        float dist = sqrtf(fmaxf(d2, 1e-12f));
        kv = expf(-LAMB * dist);
        g_Kmat[idx] = kv;
    }
    float bs = blockReduceSum(kv);
    if (threadIdx.x == 0) g_Kpart[blockIdx.x] = bs;
}

// ---------------- cluster-based persistent sinkhorn (NB CTAs x 512) ----------------
// One cluster.sync per iteration (R12-proven scheme).
template <int NB, int RW>
__global__ void __launch_bounds__(512, 1) k_sink(int writeF32) {
    const int t = threadIdx.x, w = t >> 5, lane = t & 31;
    const int blk = blockIdx.x;           // == cluster rank (single cluster)
    const int gw  = blk * 16 + w;
    const int rbase = gw * RW;
    __shared__ float scolW[16][128];
    __shared__ float sWerr[16];
    __shared__ float colsumBuf[2][128];
    __shared__ float errBuf[2];
    __shared__ float sbcast[128];
    __shared__ float sErrSh;

    // Ksum from expK partials (identical fixed-order computation in every block)
    float ks = 0.0f;
    for (int i = t; i < EXPK_BLOCKS; i += 512) ks += __ldcg(&g_Kpart[i]);
    ks = blockReduceSum(ks);
    const float invKs = 1.0f / ks;

    float Kr[RW][4], a[RW], prev[RW], b[4];
    bool rv[RW], cv[4];
    int cols[4];
    #pragma unroll
    for (int c = 0; c < 4; c++) {
        int j = lane + 32 * c;
        cols[c] = j; cv[c] = (j < WAY); b[c] = cv[c] ? 1.0f : 0.0f;
    }
    #pragma unroll
    for (int k = 0; k < RW; k++) {
        int r = rbase + k;
        rv[k] = (r < NU); a[k] = 1.0f; prev[k] = 0.0f;
        #pragma unroll
        for (int c = 0; c < 4; c++)
            Kr[k][c] = (rv[k] && cv[c]) ? g_Kmat[r * WAY + cols[c]] * invKs : 0.0f;
    }

    const uint32_t colBufAddr0 = (uint32_t)__cvta_generic_to_shared(&colsumBuf[0][0]);
    const uint32_t colBufAddr1 = (uint32_t)__cvta_generic_to_shared(&colsumBuf[1][0]);
    const uint32_t errAddr0    = (uint32_t)__cvta_generic_to_shared(&errBuf[0]);
    const uint32_t errAddr1    = (uint32_t)__cvta_generic_to_shared(&errBuf[1]);

    float rowsum[RW];
    for (int it = 0; it < 1000; ++it) {
        const int p = it & 1;
        float werr = 0.0f;
        {
            float anew[RW];
            #pragma unroll
            for (int k = 0; k < RW; k++) {
                float s = 0.0f;
                #pragma unroll
                for (int c = 0; c < 4; c++) s = fmaf(Kr[k][c], b[c], s);
                #pragma unroll
                for (int off = 16; off; off >>= 1) s += __shfl_xor_sync(0xffffffffu, s, off);
                rowsum[k] = a[k] * s;
                anew[k] = rv[k] ? a[k] / rowsum[k] : 0.0f;
                if (rv[k]) werr = fmaxf(werr, fabsf(prev[k] - rowsum[k]));
            }
            #pragma unroll
            for (int c = 0; c < 4; c++) {
                float s = 0.0f;
                #pragma unroll
                for (int k = 0; k < RW; k++) s = fmaf(Kr[k][c], anew[k], s);
                scolW[w][cols[c]] = cv[c] ? s : 0.0f;
            }
        }   // anew dead before the cluster barrier (register pressure)
        if (lane == 0) sWerr[w] = werr;
        __syncthreads();
        if (t < 128) {
            float s = scolW[0][t];
            #pragma unroll
            for (int ww = 1; ww < 16; ww++) s += scolW[ww][t];
            colsumBuf[p][t] = s;
        }
        if (t == 0) {
            float e = sWerr[0];
            #pragma unroll
            for (int ww = 1; ww < 16; ww++) e = fmaxf(e, sWerr[ww]);
            errBuf[p] = e;
        }
        CLUSTER_SYNC();
        if (t < 128) {
            uint32_t addr = (p ? colBufAddr1 : colBufAddr0) + t * 4;
            float s = 0.0f;
            #pragma unroll
            for (int bb = 0; bb < NB; bb++) s += dsmem_ld(addr, (uint32_t)bb);
            sbcast[t] = s;
        }
        if (t == 0) {
            uint32_t addr = p ? errAddr1 : errAddr0;
            float e = 0.0f;
            #pragma unroll
            for (int bb = 0; bb < NB; bb++) e = fmaxf(e, dsmem_ld(addr, (uint32_t)bb));
            sErrSh = e;
        }
        __syncthreads();
        if (sErrSh <= 1e-6f) break;     // a,b stay pre-update: exact reference semantics
        #pragma unroll
        for (int k = 0; k < RW; k++) {
            if (rv[k]) { a[k] = a[k] / rowsum[k]; prev[k] = rowsum[k]; }
        }
        #pragma unroll
        for (int c = 0; c < 4; c++) if (cv[c]) b[c] = 15.0f / sbcast[cols[c]];
        __syncthreads();                // protect sbcast before next overwrite
    }

    // epilogue: write packed Pu pairs (+ f32 on final epoch) + colP partials
    float colacc[4] = {0.f, 0.f, 0.f, 0.f};
    #pragma unroll
    for (int k = 0; k < RW; k += 2) {   // rv[k]==rv[k+1] (NU even, rbase even)
        int r = rbase + k;
        if (!rv[k]) continue;
        #pragma unroll
        for (int c = 0; c < 4; c++) {
            if (cv[c]) {
                float p0 = a[k] * Kr[k][c] * b[c];
                float p1 = a[k + 1] * Kr[k + 1][c] * b[c];
                g_PuPack[(r >> 1) * WAY + cols[c]] = bfpack(p0, p1);
                if (writeF32) {
                    g_Pu[r * WAY + cols[c]]       = p0;
                    g_Pu[(r + 1) * WAY + cols[c]] = p1;
                }
                colacc[c] += p0 + p1;
            }
        }
    }
    __syncthreads();
    #pragma unroll
    for (int c = 0; c < 4; c++) scolW[w][cols[c]] = cv[c] ? colacc[c] : 0.0f;
    __syncthreads();
    if (t < 128) {
        float s = scolW[0][t];
        #pragma unroll
        for (int ww = 1; ww < 16; ww++) s += scolW[ww][t];
        __stcg(&g_colPpart[blk * 128 + t], s);
    }
    CLUSTER_SYNC();                     // no CTA exits while peers may still read its smem
}

// ===== bf16 tensor-core epilogue GEMM from pre-packed operands
__global__ void __launch_bounds__(256) k_epi() {
    const int n0 = blockIdx.x * 64;
    const int u0 = blockIdx.y * USPL;
    const int t  = threadIdx.x;
    const int w  = t >> 5, lane = t & 31;
    const int gid = lane >> 2, tig = lane & 3;
    const int m0w = w * 16;

    __shared__ uint32_t As[128][20];  // [class][u-pair] bf16x2
    __shared__ uint32_t Bs[64][20];   // [dim][u-pair]

    float c[8][4];
    #pragma unroll
    for (int i = 0; i < 8; i++)
        #pragma unroll
        for (int jj = 0; jj < 4; jj++) c[i][jj] = 0.0f;

    const int am  = t & 127;
    const int ah  = t >> 7;
    const int bup = t >> 4;
    const int bnn = (t & 15) * 4;

    for (int kt = 0; kt < 12; kt++) {
        const int ub = kt * 32;
        const int pairBase = (u0 >> 1) + (ub >> 1);
        #pragma unroll
        for (int i = 0; i < 8; i++) {
            int kp = ah * 8 + i;
            int ul = ub + kp * 2;
            uint32_t v = 0u;
            if (am < WAY && ul < USPL && u0 + ul < NU)
                v = g_PuPack[(pairBase + kp) * WAY + am];
            As[am][kp] = v;
        }
        {
            int ul = ub + bup * 2;
            uint2 w0 = make_uint2(0u, 0u), w1 = make_uint2(0u, 0u);
            if (ul < USPL && u0 + ul < NU) {
                w0 = *(const uint2*)&g_ZuPack[(size_t)(u0 + ul) * DW + ((n0 + bnn) >> 1)];
                w1 = *(const uint2*)&g_ZuPack[(size_t)(u0 + ul + 1) * DW + ((n0 + bnn) >> 1)];
            }
            Bs[bnn + 0][bup] = prmt(w0.x, w1.x, 0x5410);
            Bs[bnn + 1][bup] = prmt(w0.x, w1.x, 0x7632);
            Bs[bnn + 2][bup] = prmt(w0.y, w1.y, 0x5410);
            Bs[bnn + 3][bup] = prmt(w0.y, w1.y, 0x7632);
        }
        __syncthreads();
        #pragma unroll
        for (int ks = 0; ks < 2; ks++) {
            const int kp = ks * 8;
            uint32_t a0 = As[m0w + gid][kp + tig];
            uint32_t a1 = As[m0w + gid + 8][kp + tig];
            uint32_t a2 = As[m0w + gid][kp + tig + 4];
            uint32_t a3 = As[m0w + gid + 8][kp + tig + 4];
            #pragma unroll
            for (int nt = 0; nt < 8; nt++) {
                uint32_t b0 = Bs[nt * 8 + gid][kp + tig];
                uint32_t b1 = Bs[nt * 8 + gid][kp + tig + 4];
                mma_bf16(c[nt], a0, a1, a2, a3, b0, b1);
            }
        }
        __syncthreads();
    }
    float* outp = g_Epart + (size_t)blockIdx.y * WAYD;
    #pragma unroll
    for (int nt = 0; nt < 8; nt++) {
        int dcol = n0 + nt * 8 + tig * 2;
        #pragma unroll
        for (int h = 0; h < 2; h++) {
            int j = m0w + gid + 8 * h;
            if (j < WAY) {
                outp[(size_t)j * D + dcol]     = c[nt][2 * h];
                outp[(size_t)j * D + dcol + 1] = c[nt][2 * h + 1];
            }
        }
    }
}

// one block per class: mus update + musPack + mn2 for next epoch
__global__ void __launch_bounds__(512) k_update(int nb) {
    const int j = blockIdx.x, t = threadIdx.x;
    __shared__ float sden;
    if (t == 0) {
        float s = 0.0f;
        for (int bb = 0; bb < nb; bb++) s += g_colPpart[bb * 128 + j];
        sden = 5.0f + s;
    }
    __syncthreads();
    const float invden = 1.0f / sden;
    float ss = 0.0f;
    #pragma unroll
    for (int q = 0; q < 4; q++) {
        int i = t + 512 * q;           // word index 0..2047
        int idx = j * D + 2 * i;
        float E0 = 0.0f, E1 = 0.0f;
        #pragma unroll
        for (int s = 0; s < 4; s++) {
            E0 += g_Epart[s * WAYD + idx];
            E1 += g_Epart[s * WAYD + idx + 1];
        }
        float em0 = (g_Sl[idx] + E0) * invden;
        float em1 = (g_Sl[idx + 1] + E1) * invden;
        float m0 = g_mus[idx],     m1 = g_mus[idx + 1];
        m0 = m0 + ALPHAC * (em0 - m0);
        m1 = m1 + ALPHAC * (em1 - m1);
        g_mus[idx] = m0; g_mus[idx + 1] = m1;
        g_musPack[j * DW + i] = bfpack(m0, m1);
        ss += m0 * m0 + m1 * m1;
    }
    ss = blockReduceSum(ss);
    if (t == 0) g_mn2[j] = ss;
}

// ---------------- output ----------------
__global__ void k_out(float* __restrict__ out) {
    int idx = blockIdx.x * blockDim.x + threadIdx.x;
    if (idx == 0) g_accN = 0;
    if (idx < NUW) out[idx] = logf(g_Pu[idx] + 1e-5f);
}

__global__ void k_acc(const int* __restrict__ labels) {
    int i = blockIdx.x * blockDim.x + threadIdx.x;
    if (i >= NU) return;
    const float* row = g_Pu + i * WAY;
    float best = row[0]; int bj = 0;
    for (int j = 1; j < WAY; j++) {
        float v = row[j];
        if (v > best) { best = v; bj = j; }
    }
    if (bj == labels[NL + i]) atomicAdd(&g_accN, 1);
}

__global__ void k_accw(float* __restrict__ out) {
    out[NUW] = (float)g_accN * (1.0f / NU);
}

// ---------------- launch ----------------
extern "C" void kernel_launch(void* const* d_in, const int* in_sizes, int n_in,
                              void* d_out, int out_size) {
    const float* X = (const float*)d_in[0];
    const int* labels = (const int*)d_in[1];
    float* out = (float*)d_out;

    // probe 16-CTA nonportable cluster support (host API, deterministic per machine)
    int nb = 8;
    {
        cudaFuncSetAttribute((const void*)k_sink<16, 6>,
                             cudaFuncAttributeNonPortableClusterSizeAllowed, 1);
        cudaLaunchConfig_t pc = {};
        pc.gridDim = dim3(16, 1, 1);
        pc.blockDim = dim3(512, 1, 1);
        int cs = 0;
        cudaError_t err = cudaOccupancyMaxPotentialClusterSize(
            &cs, (const void*)k_sink<16, 6>, &pc);
        if (err == cudaSuccess && cs >= 16) nb = 16;
        else cudaGetLastError();
    }

    k_pre1<<<NTOT, 256>>>(X);
    k_colmeans<<<D / 64, 256>>>();
    k_pre2<<<NTOT, 256>>>();
    k_Sl<<<WAY, 512>>>();

    cudaLaunchConfig_t cfg = {};
    cudaLaunchAttribute attrs[1];
    attrs[0].id = cudaLaunchAttributeClusterDimension;
    attrs[0].val.clusterDim.x = nb;
    attrs[0].val.clusterDim.y = 1;
    attrs[0].val.clusterDim.z = 1;
    cfg.gridDim = dim3(nb, 1, 1);
    cfg.blockDim = dim3(512, 1, 1);
    cfg.attrs = attrs;
    cfg.numAttrs = 1;

    for (int e = 0; e < 21; e++) {
        k_gram<<<dim3(24, KSPL), 256>>>();
        k_expK<<<EXPK_BLOCKS, 256>>>();
        int wf = (e == 20) ? 1 : 0;
        if (nb == 16) cudaLaunchKernelEx(&cfg, k_sink<16, 6>, wf);
        else          cudaLaunchKernelEx(&cfg, k_sink<8, 12>, wf);
        if (e < 20) {
            k_epi<<<dim3(64, 4), 256>>>();
            k_update<<<WAY, 512>>>(nb);
        }
    }
    k_out<<<(NUW + 255) / 256, 256>>>(out);
    k_acc<<<(NU + 255) / 256, 256>>>(labels);
    if (out_size > NUW) k_accw<<<1, 1>>>(out);
}

// round 15
// speedup vs baseline: 1.2721x; 1.1349x over previous
#include <cuda_runtime.h>
#include <math.h>
#include <stdint.h>

// ---------------- problem constants ----------------
constexpr int D      = 4096;
constexpr int DW     = D / 2;          // 2048 bf16x2 words per row
constexpr int NTOT   = 2000;
constexpr int NL     = 500;
constexpr int NU     = 1500;
constexpr int WAY    = 100;
constexpr int NUW    = NU * WAY;      // 150000
constexpr int WAYD   = WAY * D;       // 409600
constexpr float LAMB   = 10.0f;
constexpr float ALPHAC = 0.2f;
constexpr int KSPL   = 8;              // gram k-splits (R12-proven geometry)
constexpr int EXPK_BLOCKS = (NUW + 255) / 256;   // 586
constexpr int USPL   = 376;            // epi u-split (pair-aligned)

// ---------------- device scratch ----------------
__device__ float g_X1[NTOT * D];
__device__ float g_Z[NTOT * D];
__device__ uint32_t g_ZuPack[NU * DW];     // bf16x2 (d-paired) unlabeled features
__device__ uint32_t g_musPack[WAY * DW];   // bf16x2 (d-paired) class means
__device__ uint32_t g_PuPack[(NU / 2) * WAY]; // bf16x2 (u-paired) transport plan
__device__ float g_zn2[NTOT];
__device__ float g_meanL[D], g_meanU[D];
__device__ float g_Sl[WAYD];
__device__ float g_mus[WAYD];
__device__ float g_mn2[WAY];
__device__ float g_Cpart[KSPL * NUW];
__device__ float g_Kmat[NUW];
__device__ float g_Kpart[600];
__device__ float g_Pu[NUW];
__device__ float g_colPpart[16 * 128];
__device__ float g_Epart[4 * WAYD];
__device__ int   g_accN;

// ---------------- helpers ----------------
__device__ __forceinline__ float blockReduceSum(float v) {
    static __shared__ float sh[32];
    __syncthreads();
    int lane = threadIdx.x & 31, wid = threadIdx.x >> 5;
    #pragma unroll
    for (int off = 16; off; off >>= 1) v += __shfl_xor_sync(0xffffffffu, v, off);
    if (lane == 0) sh[wid] = v;
    __syncthreads();
    int nw = (blockDim.x + 31) >> 5;
    float r = 0.0f;
    if (wid == 0) {
        r = (lane < nw) ? sh[lane] : 0.0f;
        #pragma unroll
        for (int off = 16; off; off >>= 1) r += __shfl_xor_sync(0xffffffffu, r, off);
        if (lane == 0) sh[0] = r;
    }
    __syncthreads();
    return sh[0];
}

// pack two floats into bf16x2 (lo in low half, hi in high half)
__device__ __forceinline__ uint32_t bfpack(float lo, float hi) {
    uint32_t r;
    asm("cvt.rn.bf16x2.f32 %0, %1, %2;" : "=r"(r) : "f"(hi), "f"(lo));
    return r;
}

__device__ __forceinline__ uint32_t prmt(uint32_t a, uint32_t b, uint32_t sel) {
    uint32_t r;
    asm("prmt.b32 %0, %1, %2, %3;" : "=r"(r) : "r"(a), "r"(b), "r"(sel));
    return r;
}

__device__ __forceinline__ void mma_bf16(float c[4], uint32_t a0, uint32_t a1,
                                         uint32_t a2, uint32_t a3,
                                         uint32_t b0, uint32_t b1) {
    asm volatile(
        "mma.sync.aligned.m16n8k16.row.col.f32.bf16.bf16.f32 "
        "{%0,%1,%2,%3}, {%4,%5,%6,%7}, {%8,%9}, {%0,%1,%2,%3};\n"
        : "+f"(c[0]), "+f"(c[1]), "+f"(c[2]), "+f"(c[3])
        : "r"(a0), "r"(a1), "r"(a2), "r"(a3), "r"(b0), "r"(b1));
}

__device__ __forceinline__ float dsmem_ld(uint32_t local_addr, uint32_t rank) {
    float v;
    asm volatile(
        "{\n\t"
        ".reg .b32 ra;\n\t"
        "mapa.shared::cluster.u32 ra, %1, %2;\n\t"
        "ld.shared::cluster.f32 %0, [ra];\n\t"
        "}"
        : "=f"(v) : "r"(local_addr), "r"(rank));
    return v;
}

#define CLUSTER_SYNC() do { \
    asm volatile("barrier.cluster.arrive.aligned;" ::: "memory"); \
    asm volatile("barrier.cluster.wait.aligned;" ::: "memory"); \
} while (0)

// ---------------- preprocessing ----------------
__global__ void k_pre1(const float* __restrict__ X) {
    int row = blockIdx.x, t = threadIdx.x;
    __shared__ float buf[D];
    float ss = 0.0f;
    for (int d = t; d < D; d += blockDim.x) {
        float v = sqrtf(X[(size_t)row * D + d] + 1e-6f);
        buf[d] = v; ss += v * v;
    }
    ss = blockReduceSum(ss);
    float inv = 1.0f / fmaxf(sqrtf(ss), 1e-12f);
    for (int d = t; d < D; d += blockDim.x) g_X1[(size_t)row * D + d] = buf[d] * inv;
}

__global__ void k_colmeans() {
    int lane = threadIdx.x & 63;
    int part = threadIdx.x >> 6;         // 0..3
    int d = blockIdx.x * 64 + lane;
    __shared__ float sh[4][64];
    float sL = 0.0f;
    for (int i = part * 125; i < (part + 1) * 125; i++) sL += g_X1[(size_t)i * D + d];
    sh[part][lane] = sL;
    __syncthreads();
    if (part == 0)
        g_meanL[d] = (sh[0][lane] + sh[1][lane] + sh[2][lane] + sh[3][lane]) * (1.0f / NL);
    __syncthreads();
    float sU = 0.0f;
    for (int i = NL + part * 375; i < NL + (part + 1) * 375; i++) sU += g_X1[(size_t)i * D + d];
    sh[part][lane] = sU;
    __syncthreads();
    if (part == 0)
        g_meanU[d] = (sh[0][lane] + sh[1][lane] + sh[2][lane] + sh[3][lane]) * (1.0f / NU);
}

__global__ void k_pre2() {
    int row = blockIdx.x, t = threadIdx.x;
    __shared__ float buf[D];
    const float* mean = (row < NL) ? g_meanL : g_meanU;
    float ss = 0.0f;
    for (int d = t; d < D; d += 256) {
        float v = g_X1[(size_t)row * D + d] - mean[d];
        buf[d] = v; ss += v * v;
    }
    ss = blockReduceSum(ss);
    float inv = 1.0f / fmaxf(sqrtf(ss), 1e-12f);
    if (t == 0) g_zn2[row] = ss * inv * inv;
    for (int i = t; i < DW; i += 256) {
        float lo = buf[2 * i] * inv, hi = buf[2 * i + 1] * inv;
        ((float2*)g_Z)[(size_t)row * DW + i] = make_float2(lo, hi);
        if (row >= NL) g_ZuPack[(size_t)(row - NL) * DW + i] = bfpack(lo, hi);
    }
}

// one block (512 thr) per class: Sl, mus0, musPack, mn2
__global__ void __launch_bounds__(512) k_Sl() {
    int c = blockIdx.x, t = threadIdx.x;
    float ss = 0.0f;
    #pragma unroll
    for (int q = 0; q < 4; q++) {
        int i = t + 512 * q;           // word index 0..2047
        int d0 = 2 * i;
        float s0 = 0.0f, s1 = 0.0f;
        #pragma unroll
        for (int k = 0; k < 5; k++) {
            float2 z = ((const float2*)g_Z)[(size_t)(k * WAY + c) * DW + i];
            s0 += z.x; s1 += z.y;
        }
        g_Sl[c * D + d0] = s0; g_Sl[c * D + d0 + 1] = s1;
        float m0 = s0 * 0.2f, m1 = s1 * 0.2f;
        g_mus[c * D + d0] = m0; g_mus[c * D + d0 + 1] = m1;
        g_musPack[c * DW + i] = bfpack(m0, m1);
        ss += m0 * m0 + m1 * m1;
    }
    ss = blockReduceSum(ss);
    if (t == 0) g_mn2[c] = ss;
}

// ===== bf16 tensor-core gram from pre-packed operands (8 k-splits of 512)
__global__ void __launch_bounds__(256) k_gram() {
    const int r0 = blockIdx.x * 64;
    const int k0 = blockIdx.y * 512;
    const int t  = threadIdx.x;
    const int w  = t >> 5, lane = t & 31;
    const int gid = lane >> 2, tig = lane & 3;
    const int m0w = (w >> 1) * 16;
    const int n0w = (w & 1) * 56;

    __shared__ uint32_t As[64][36];   // [m][k-pair] bf16x2 (stride 36: conflict-free)
    __shared__ uint32_t Bs[112][36];  // [n][k-pair]

    float c[7][4];
    #pragma unroll
    for (int i = 0; i < 7; i++)
        #pragma unroll
        for (int jj = 0; jj < 4; jj++) c[i][jj] = 0.0f;

    const int arow = t >> 2;          // 0..63
    const int af4  = t & 3;

    for (int kt = 0; kt < 512; kt += 64) {
        const int kw = (k0 + kt) >> 1;      // word base
        #pragma unroll
        for (int i = 0; i < 4; i++) {
            int f4 = af4 + 4 * i;
            uint2 v = make_uint2(0u, 0u);
            if (r0 + arow < NU) v = *(const uint2*)&g_ZuPack[(size_t)(r0 + arow) * DW + kw + f4 * 2];
            As[arow][f4 * 2]     = v.x;
            As[arow][f4 * 2 + 1] = v.y;
        }
        #pragma unroll
        for (int i = 0; i < 7; i++) {
            int idx = t + 256 * i;
            int row = idx >> 4, f4 = idx & 15;
            uint2 v = make_uint2(0u, 0u);
            if (row < WAY) v = *(const uint2*)&g_musPack[(size_t)row * DW + kw + f4 * 2];
            Bs[row][f4 * 2]     = v.x;
            Bs[row][f4 * 2 + 1] = v.y;
        }
        __syncthreads();
        #pragma unroll
        for (int ks = 0; ks < 4; ks++) {
            const int kp = ks * 8;
            uint32_t a0 = As[m0w + gid][kp + tig];
            uint32_t a1 = As[m0w + gid + 8][kp + tig];
            uint32_t a2 = As[m0w + gid][kp + tig + 4];
            uint32_t a3 = As[m0w + gid + 8][kp + tig + 4];
            #pragma unroll
            for (int nt = 0; nt < 7; nt++) {
                uint32_t b0 = Bs[n0w + nt * 8 + gid][kp + tig];
                uint32_t b1 = Bs[n0w + nt * 8 + gid][kp + tig + 4];
                mma_bf16(c[nt], a0, a1, a2, a3, b0, b1);
            }
        }
        __syncthreads();
    }
    float* out = g_Cpart + (size_t)blockIdx.y * NUW;
    #pragma unroll
    for (int nt = 0; nt < 7; nt++) {
        int j0 = n0w + nt * 8 + tig * 2;
        int gr0 = r0 + m0w + gid;
        #pragma unroll
        for (int h = 0; h < 2; h++) {
            int gr = gr0 + 8 * h;
            if (gr < NU) {
                if (j0 < WAY)     out[gr * WAY + j0]     = c[nt][2 * h];
                if (j0 + 1 < WAY) out[gr * WAY + j0 + 1] = c[nt][2 * h + 1];
            }
        }
    }
}

// K = exp(-lam*dist); wide grid (memory phase stays chip-wide — R5/R10 lesson)
__global__ void k_expK() {
    int idx = blockIdx.x * blockDim.x + threadIdx.x;
    float kv = 0.0f;
    if (idx < NUW) {
        int i = idx / WAY, j = idx - i * WAY;
        float c = 0.0f;
        #pragma unroll
        for (int s = 0; s < KSPL; s++) c += g_Cpart[s * NUW + idx];
        float d2 = g_zn2[NL + i] + g_mn2[j] - 2.0f * c;
        float dist = sqrtf(fmaxf(d2, 1e-12f));
        kv = expf(-LAMB * dist);
        g_Kmat[idx] = kv;
    }
    float bs = blockReduceSum(kv);
    if (threadIdx.x == 0) g_Kpart[blockIdx.x] = bs;
}

// ---------------- cluster-based persistent sinkhorn (NB CTAs x 512) ----------------
// One cluster.sync per iteration (R12-proven scheme).
template <int NB, int RW>
__global__ void __launch_bounds__(512, 1) k_sink(int writeF32) {
    const int t = threadIdx.x, w = t >> 5, lane = t & 31;
    const int blk = blockIdx.x;           // == cluster rank (single cluster)
    const int gw  = blk * 16 + w;
    const int rbase = gw * RW;
    __shared__ float scolW[16][128];
    __shared__ float sWerr[16];
    __shared__ float colsumBuf[2][128];
    __shared__ float errBuf[2];
    __shared__ float sbcast[128];
    __shared__ float sErrSh;

    // Ksum from expK partials (identical fixed-order computation in every block)
    float ks = 0.0f;
    for (int i = t; i < EXPK_BLOCKS; i += 512) ks += __ldcg(&g_Kpart[i]);
    ks = blockReduceSum(ks);
    const float invKs = 1.0f / ks;

    float Kr[RW][4], a[RW], prev[RW], b[4];
    bool rv[RW], cv[4];
    int cols[4];
    #pragma unroll
    for (int c = 0; c < 4; c++) {
        int j = lane + 32 * c;
        cols[c] = j; cv[c] = (j < WAY); b[c] = cv[c] ? 1.0f : 0.0f;
    }
    #pragma unroll
    for (int k = 0; k < RW; k++) {
        int r = rbase + k;
        rv[k] = (r < NU); a[k] = 1.0f; prev[k] = 0.0f;
        #pragma unroll
        for (int c = 0; c < 4; c++)
            Kr[k][c] = (rv[k] && cv[c]) ? g_Kmat[r * WAY + cols[c]] * invKs : 0.0f;
    }

    const uint32_t colBufAddr0 = (uint32_t)__cvta_generic_to_shared(&colsumBuf[0][0]);
    const uint32_t colBufAddr1 = (uint32_t)__cvta_generic_to_shared(&colsumBuf[1][0]);
    const uint32_t errAddr0    = (uint32_t)__cvta_generic_to_shared(&errBuf[0]);
    const uint32_t errAddr1    = (uint32_t)__cvta_generic_to_shared(&errBuf[1]);

    float rowsum[RW];
    for (int it = 0; it < 1000; ++it) {
        const int p = it & 1;
        float werr = 0.0f;
        {
            float anew[RW];
            #pragma unroll
            for (int k = 0; k < RW; k++) {
                float s = 0.0f;
                #pragma unroll
                for (int c = 0; c < 4; c++) s = fmaf(Kr[k][c], b[c], s);
                #pragma unroll
                for (int off = 16; off; off >>= 1) s += __shfl_xor_sync(0xffffffffu, s, off);
                rowsum[k] = a[k] * s;
                anew[k] = rv[k] ? a[k] / rowsum[k] : 0.0f;
                if (rv[k]) werr = fmaxf(werr, fabsf(prev[k] - rowsum[k]));
            }
            #pragma unroll
            for (int c = 0; c < 4; c++) {
                float s = 0.0f;
                #pragma unroll
                for (int k = 0; k < RW; k++) s = fmaf(Kr[k][c], anew[k], s);
                scolW[w][cols[c]] = cv[c] ? s : 0.0f;
            }
        }   // anew dead before the cluster barrier (register pressure)
        if (lane == 0) sWerr[w] = werr;
        __syncthreads();
        if (t < 128) {
            float s = scolW[0][t];
            #pragma unroll
            for (int ww = 1; ww < 16; ww++) s += scolW[ww][t];
            colsumBuf[p][t] = s;
        }
        if (t == 0) {
            float e = sWerr[0];
            #pragma unroll
            for (int ww = 1; ww < 16; ww++) e = fmaxf(e, sWerr[ww]);
            errBuf[p] = e;
        }
        CLUSTER_SYNC();
        if (t < 128) {
            uint32_t addr = (p ? colBufAddr1 : colBufAddr0) + t * 4;
            float s = 0.0f;
            #pragma unroll
            for (int bb = 0; bb < NB; bb++) s += dsmem_ld(addr, (uint32_t)bb);
            sbcast[t] = s;
        }
        if (t == 0) {
            uint32_t addr = p ? errAddr1 : errAddr0;
            float e = 0.0f;
            #pragma unroll
            for (int bb = 0; bb < NB; bb++) e = fmaxf(e, dsmem_ld(addr, (uint32_t)bb));
            sErrSh = e;
        }
        __syncthreads();
        if (sErrSh <= 1e-6f) break;     // a,b stay pre-update: exact reference semantics
        #pragma unroll
        for (int k = 0; k < RW; k++) {
            if (rv[k]) { a[k] = a[k] / rowsum[k]; prev[k] = rowsum[k]; }
        }
        #pragma unroll
        for (int c = 0; c < 4; c++) if (cv[c]) b[c] = 15.0f / sbcast[cols[c]];
        __syncthreads();                // protect sbcast before next overwrite
    }

    // epilogue: write packed Pu pairs (+ f32 on final epoch) + colP partials
    float colacc[4] = {0.f, 0.f, 0.f, 0.f};
    #pragma unroll
    for (int k = 0; k < RW; k += 2) {   // rv[k]==rv[k+1] (NU even, rbase even)
        int r = rbase + k;
        if (!rv[k]) continue;
        #pragma unroll
        for (int c = 0; c < 4; c++) {
            if (cv[c]) {
                float p0 = a[k] * Kr[k][c] * b[c];
                float p1 = a[k + 1] * Kr[k + 1][c] * b[c];
                g_PuPack[(r >> 1) * WAY + cols[c]] = bfpack(p0, p1);
                if (writeF32) {
                    g_Pu[r * WAY + cols[c]]       = p0;
                    g_Pu[(r + 1) * WAY + cols[c]] = p1;
                }
                colacc[c] += p0 + p1;
            }
        }
    }
    __syncthreads();
    #pragma unroll
    for (int c = 0; c < 4; c++) scolW[w][cols[c]] = cv[c] ? colacc[c] : 0.0f;
    __syncthreads();
    if (t < 128) {
        float s = scolW[0][t];
        #pragma unroll
        for (int ww = 1; ww < 16; ww++) s += scolW[ww][t];
        __stcg(&g_colPpart[blk * 128 + t], s);
    }
    CLUSTER_SYNC();                     // no CTA exits while peers may still read its smem
}

// ===== bf16 tensor-core epilogue GEMM from pre-packed operands
__global__ void __launch_bounds__(256) k_epi() {
    const int n0 = blockIdx.x * 64;
    const int u0 = blockIdx.y * USPL;
    const int t  = threadIdx.x;
    const int w  = t >> 5, lane = t & 31;
    const int gid = lane >> 2, tig = lane & 3;
    const int m0w = w * 16;

    __shared__ uint32_t As[128][20];  // [class][u-pair] bf16x2
    __shared__ uint32_t Bs[64][20];   // [dim][u-pair]

    float c[8][4];
    #pragma unroll
    for (int i = 0; i < 8; i++)
        #pragma unroll
        for (int jj = 0; jj < 4; jj++) c[i][jj] = 0.0f;

    const int am  = t & 127;
    const int ah  = t >> 7;
    const int bup = t >> 4;
    const int bnn = (t & 15) * 4;

    for (int kt = 0; kt < 12; kt++) {
        const int ub = kt * 32;
        const int pairBase = (u0 >> 1) + (ub >> 1);
        #pragma unroll
        for (int i = 0; i < 8; i++) {
            int kp = ah * 8 + i;
            int ul = ub + kp * 2;
            uint32_t v = 0u;
            if (am < WAY && ul < USPL && u0 + ul < NU)
                v = g_PuPack[(pairBase + kp) * WAY + am];
            As[am][kp] = v;
        }
        {
            int ul = ub + bup * 2;
            uint2 w0 = make_uint2(0u, 0u), w1 = make_uint2(0u, 0u);
            if (ul < USPL && u0 + ul < NU) {
                w0 = *(const uint2*)&g_ZuPack[(size_t)(u0 + ul) * DW + ((n0 + bnn) >> 1)];
                w1 = *(const uint2*)&g_ZuPack[(size_t)(u0 + ul + 1) * DW + ((n0 + bnn) >> 1)];
            }
            Bs[bnn + 0][bup] = prmt(w0.x, w1.x, 0x5410);
            Bs[bnn + 1][bup] = prmt(w0.x, w1.x, 0x7632);
            Bs[bnn + 2][bup] = prmt(w0.y, w1.y, 0x5410);
            Bs[bnn + 3][bup] = prmt(w0.y, w1.y, 0x7632);
        }
        __syncthreads();
        #pragma unroll
        for (int ks = 0; ks < 2; ks++) {
            const int kp = ks * 8;
            uint32_t a0 = As[m0w + gid][kp + tig];
            uint32_t a1 = As[m0w + gid + 8][kp + tig];
            uint32_t a2 = As[m0w + gid][kp + tig + 4];
            uint32_t a3 = As[m0w + gid + 8][kp + tig + 4];
            #pragma unroll
            for (int nt = 0; nt < 8; nt++) {
                uint32_t b0 = Bs[nt * 8 + gid][kp + tig];
                uint32_t b1 = Bs[nt * 8 + gid][kp + tig + 4];
                mma_bf16(c[nt], a0, a1, a2, a3, b0, b1);
            }
        }
        __syncthreads();
    }
    float* outp = g_Epart + (size_t)blockIdx.y * WAYD;
    #pragma unroll
    for (int nt = 0; nt < 8; nt++) {
        int dcol = n0 + nt * 8 + tig * 2;
        #pragma unroll
        for (int h = 0; h < 2; h++) {
            int j = m0w + gid + 8 * h;
            if (j < WAY) {
                outp[(size_t)j * D + dcol]     = c[nt][2 * h];
                outp[(size_t)j * D + dcol + 1] = c[nt][2 * h + 1];
            }
        }
    }
}

// one block per class: mus update + musPack + mn2 for next epoch
__global__ void __launch_bounds__(512) k_update(int nb) {
    const int j = blockIdx.x, t = threadIdx.x;
    __shared__ float sden;
    if (t == 0) {
        float s = 0.0f;
        for (int bb = 0; bb < nb; bb++) s += g_colPpart[bb * 128 + j];
        sden = 5.0f + s;
    }
    __syncthreads();
    const float invden = 1.0f / sden;
    float ss = 0.0f;
    #pragma unroll
    for (int q = 0; q < 4; q++) {
        int i = t + 512 * q;           // word index 0..2047
        int idx = j * D + 2 * i;
        float E0 = 0.0f, E1 = 0.0f;
        #pragma unroll
        for (int s = 0; s < 4; s++) {
            E0 += g_Epart[s * WAYD + idx];
            E1 += g_Epart[s * WAYD + idx + 1];
        }
        float em0 = (g_Sl[idx] + E0) * invden;
        float em1 = (g_Sl[idx + 1] + E1) * invden;
        float m0 = g_mus[idx],     m1 = g_mus[idx + 1];
        m0 = m0 + ALPHAC * (em0 - m0);
        m1 = m1 + ALPHAC * (em1 - m1);
        g_mus[idx] = m0; g_mus[idx + 1] = m1;
        g_musPack[j * DW + i] = bfpack(m0, m1);
        ss += m0 * m0 + m1 * m1;
    }
    ss = blockReduceSum(ss);
    if (t == 0) g_mn2[j] = ss;
}

// ---------------- output ----------------
__global__ void k_out(float* __restrict__ out) {
    int idx = blockIdx.x * blockDim.x + threadIdx.x;
    if (idx == 0) g_accN = 0;
    if (idx < NUW) out[idx] = logf(g_Pu[idx] + 1e-5f);
}

__global__ void k_acc(const int* __restrict__ labels) {
    int i = blockIdx.x * blockDim.x + threadIdx.x;
    if (i >= NU) return;
    const float* row = g_Pu + i * WAY;
    float best = row[0]; int bj = 0;
    for (int j = 1; j < WAY; j++) {
        float v = row[j];
        if (v > best) { best = v; bj = j; }
    }
    if (bj == labels[NL + i]) atomicAdd(&g_accN, 1);
}

__global__ void k_accw(float* __restrict__ out) {
    out[NUW] = (float)g_accN * (1.0f / NU);
}

// ---------------- launch ----------------
extern "C" void kernel_launch(void* const* d_in, const int* in_sizes, int n_in,
                              void* d_out, int out_size) {
    const float* X = (const float*)d_in[0];
    const int* labels = (const int*)d_in[1];
    float* out = (float*)d_out;

    // probe 16-CTA nonportable cluster support (host API, deterministic per machine)
    int nb = 8;
    {
        cudaFuncSetAttribute((const void*)k_sink<16, 6>,
                             cudaFuncAttributeNonPortableClusterSizeAllowed, 1);
        cudaLaunchConfig_t pc = {};
        pc.gridDim = dim3(16, 1, 1);
        pc.blockDim = dim3(512, 1, 1);
        int cs = 0;
        cudaError_t err = cudaOccupancyMaxPotentialClusterSize(
            &cs, (const void*)k_sink<16, 6>, &pc);
        if (err == cudaSuccess && cs >= 16) nb = 16;
        else cudaGetLastError();
    }

    k_pre1<<<NTOT, 256>>>(X);
    k_colmeans<<<D / 64, 256>>>();
    k_pre2<<<NTOT, 256>>>();
    k_Sl<<<WAY, 512>>>();

    cudaLaunchConfig_t cfg = {};
    cudaLaunchAttribute attrs[1];
    attrs[0].id = cudaLaunchAttributeClusterDimension;
    attrs[0].val.clusterDim.x = nb;
    attrs[0].val.clusterDim.y = 1;
    attrs[0].val.clusterDim.z = 1;
    cfg.gridDim = dim3(nb, 1, 1);
    cfg.blockDim = dim3(512, 1, 1);
    cfg.attrs = attrs;
    cfg.numAttrs = 1;

    for (int e = 0; e < 21; e++) {
        k_gram<<<dim3(24, KSPL), 256>>>();
        k_expK<<<EXPK_BLOCKS, 256>>>();
        int wf = (e == 20) ? 1 : 0;
        if (nb == 16) cudaLaunchKernelEx(&cfg, k_sink<16, 6>, wf);
        else          cudaLaunchKernelEx(&cfg, k_sink<8, 12>, wf);
        if (e < 20) {
            k_epi<<<dim3(64, 4), 256>>>();
            k_update<<<WAY, 512>>>(nb);
        }
    }
    k_out<<<(NUW + 255) / 256, 256>>>(out);
    k_acc<<<(NU + 255) / 256, 256>>>(labels);
    if (out_size > NUW) k_accw<<<1, 1>>>(out);
}

// round 16
// speedup vs baseline: 1.2786x; 1.0051x over previous
#include <cuda_runtime.h>
#include <math.h>
#include <stdint.h>

// ---------------- problem constants ----------------
constexpr int D      = 4096;
constexpr int DW     = D / 2;          // 2048 bf16x2 words per row
constexpr int NTOT   = 2000;
constexpr int NL     = 500;
constexpr int NU     = 1500;
constexpr int WAY    = 100;
constexpr int NUW    = NU * WAY;      // 150000
constexpr int WAYD   = WAY * D;       // 409600
constexpr float LAMB   = 10.0f;
constexpr float ALPHAC = 0.2f;
constexpr int KSPL   = 8;              // gram k-splits (R12-proven geometry)
constexpr int EXPK_BLOCKS = (NUW + 255) / 256;   // 586
constexpr int USPL   = 376;            // epi u-split (pair-aligned)
constexpr int ERRSLOT = 112;           // colsum exchange slot carrying err (cols use 0..99)

// ---------------- device scratch ----------------
__device__ float g_X1[NTOT * D];
__device__ float g_Z[NTOT * D];
__device__ uint32_t g_ZuPack[NU * DW];     // bf16x2 (d-paired) unlabeled features
__device__ uint32_t g_musPack[WAY * DW];   // bf16x2 (d-paired) class means
__device__ uint32_t g_PuPack[(NU / 2) * WAY]; // bf16x2 (u-paired) transport plan
__device__ float g_zn2[NTOT];
__device__ float g_meanL[D], g_meanU[D];
__device__ float g_Sl[WAYD];
__device__ float g_mus[WAYD];
__device__ float g_mn2[WAY];
__device__ float g_Cpart[KSPL * NUW];
__device__ float g_Kmat[NUW];
__device__ float g_Kpart[600];
__device__ float g_Pu[NUW];
__device__ float g_colPpart[16 * 128];
__device__ float g_Epart[4 * WAYD];
__device__ int   g_accN;

// ---------------- helpers ----------------
__device__ __forceinline__ float blockReduceSum(float v) {
    static __shared__ float sh[32];
    __syncthreads();
    int lane = threadIdx.x & 31, wid = threadIdx.x >> 5;
    #pragma unroll
    for (int off = 16; off; off >>= 1) v += __shfl_xor_sync(0xffffffffu, v, off);
    if (lane == 0) sh[wid] = v;
    __syncthreads();
    int nw = (blockDim.x + 31) >> 5;
    float r = 0.0f;
    if (wid == 0) {
        r = (lane < nw) ? sh[lane] : 0.0f;
        #pragma unroll
        for (int off = 16; off; off >>= 1) r += __shfl_xor_sync(0xffffffffu, r, off);
        if (lane == 0) sh[0] = r;
    }
    __syncthreads();
    return sh[0];
}

// pack two floats into bf16x2 (lo in low half, hi in high half)
__device__ __forceinline__ uint32_t bfpack(float lo, float hi) {
    uint32_t r;
    asm("cvt.rn.bf16x2.f32 %0, %1, %2;" : "=r"(r) : "f"(hi), "f"(lo));
    return r;
}

__device__ __forceinline__ uint32_t prmt(uint32_t a, uint32_t b, uint32_t sel) {
    uint32_t r;
    asm("prmt.b32 %0, %1, %2, %3;" : "=r"(r) : "r"(a), "r"(b), "r"(sel));
    return r;
}

__device__ __forceinline__ void mma_bf16(float c[4], uint32_t a0, uint32_t a1,
                                         uint32_t a2, uint32_t a3,
                                         uint32_t b0, uint32_t b1) {
    asm volatile(
        "mma.sync.aligned.m16n8k16.row.col.f32.bf16.bf16.f32 "
        "{%0,%1,%2,%3}, {%4,%5,%6,%7}, {%8,%9}, {%0,%1,%2,%3};\n"
        : "+f"(c[0]), "+f"(c[1]), "+f"(c[2]), "+f"(c[3])
        : "r"(a0), "r"(a1), "r"(a2), "r"(a3), "r"(b0), "r"(b1));
}

__device__ __forceinline__ float dsmem_ld(uint32_t local_addr, uint32_t rank) {
    float v;
    asm volatile(
        "{\n\t"
        ".reg .b32 ra;\n\t"
        "mapa.shared::cluster.u32 ra, %1, %2;\n\t"
        "ld.shared::cluster.f32 %0, [ra];\n\t"
        "}"
        : "=f"(v) : "r"(local_addr), "r"(rank));
    return v;
}

#define CLUSTER_SYNC() do { \
    asm volatile("barrier.cluster.arrive.aligned;" ::: "memory"); \
    asm volatile("barrier.cluster.wait.aligned;" ::: "memory"); \
} while (0)

// ---------------- preprocessing ----------------
__global__ void k_pre1(const float* __restrict__ X) {
    int row = blockIdx.x, t = threadIdx.x;
    if (row == 0 && t == 0) g_accN = 0;
    __shared__ float buf[D];
    float ss = 0.0f;
    for (int d = t; d < D; d += blockDim.x) {
        float v = sqrtf(X[(size_t)row * D + d] + 1e-6f);
        buf[d] = v; ss += v * v;
    }
    ss = blockReduceSum(ss);
    float inv = 1.0f / fmaxf(sqrtf(ss), 1e-12f);
    for (int d = t; d < D; d += blockDim.x) g_X1[(size_t)row * D + d] = buf[d] * inv;
}

__global__ void k_colmeans() {
    int lane = threadIdx.x & 63;
    int part = threadIdx.x >> 6;         // 0..3
    int d = blockIdx.x * 64 + lane;
    __shared__ float sh[4][64];
    float sL = 0.0f;
    for (int i = part * 125; i < (part + 1) * 125; i++) sL += g_X1[(size_t)i * D + d];
    sh[part][lane] = sL;
    __syncthreads();
    if (part == 0)
        g_meanL[d] = (sh[0][lane] + sh[1][lane] + sh[2][lane] + sh[3][lane]) * (1.0f / NL);
    __syncthreads();
    float sU = 0.0f;
    for (int i = NL + part * 375; i < NL + (part + 1) * 375; i++) sU += g_X1[(size_t)i * D + d];
    sh[part][lane] = sU;
    __syncthreads();
    if (part == 0)
        g_meanU[d] = (sh[0][lane] + sh[1][lane] + sh[2][lane] + sh[3][lane]) * (1.0f / NU);
}

__global__ void k_pre2() {
    int row = blockIdx.x, t = threadIdx.x;
    __shared__ float buf[D];
    const float* mean = (row < NL) ? g_meanL : g_meanU;
    float ss = 0.0f;
    for (int d = t; d < D; d += 256) {
        float v = g_X1[(size_t)row * D + d] - mean[d];
        buf[d] = v; ss += v * v;
    }
    ss = blockReduceSum(ss);
    float inv = 1.0f / fmaxf(sqrtf(ss), 1e-12f);
    if (t == 0) g_zn2[row] = ss * inv * inv;
    for (int i = t; i < DW; i += 256) {
        float lo = buf[2 * i] * inv, hi = buf[2 * i + 1] * inv;
        ((float2*)g_Z)[(size_t)row * DW + i] = make_float2(lo, hi);
        if (row >= NL) g_ZuPack[(size_t)(row - NL) * DW + i] = bfpack(lo, hi);
    }
}

// one block (512 thr) per class: Sl, mus0, musPack, mn2
__global__ void __launch_bounds__(512) k_Sl() {
    int c = blockIdx.x, t = threadIdx.x;
    float ss = 0.0f;
    #pragma unroll
    for (int q = 0; q < 4; q++) {
        int i = t + 512 * q;           // word index 0..2047
        int d0 = 2 * i;
        float s0 = 0.0f, s1 = 0.0f;
        #pragma unroll
        for (int k = 0; k < 5; k++) {
            float2 z = ((const float2*)g_Z)[(size_t)(k * WAY + c) * DW + i];
            s0 += z.x; s1 += z.y;
        }
        g_Sl[c * D + d0] = s0; g_Sl[c * D + d0 + 1] = s1;
        float m0 = s0 * 0.2f, m1 = s1 * 0.2f;
        g_mus[c * D + d0] = m0; g_mus[c * D + d0 + 1] = m1;
        g_musPack[c * DW + i] = bfpack(m0, m1);
        ss += m0 * m0 + m1 * m1;
    }
    ss = blockReduceSum(ss);
    if (t == 0) g_mn2[c] = ss;
}

// ===== bf16 tensor-core gram from pre-packed operands (8 k-splits of 512)
__global__ void __launch_bounds__(256) k_gram() {
    const int r0 = blockIdx.x * 64;
    const int k0 = blockIdx.y * 512;
    const int t  = threadIdx.x;
    const int w  = t >> 5, lane = t & 31;
    const int gid = lane >> 2, tig = lane & 3;
    const int m0w = (w >> 1) * 16;
    const int n0w = (w & 1) * 56;

    __shared__ uint32_t As[64][36];   // [m][k-pair] bf16x2 (stride 36: conflict-free)
    __shared__ uint32_t Bs[112][36];  // [n][k-pair]

    float c[7][4];
    #pragma unroll
    for (int i = 0; i < 7; i++)
        #pragma unroll
        for (int jj = 0; jj < 4; jj++) c[i][jj] = 0.0f;

    const int arow = t >> 2;          // 0..63
    const int af4  = t & 3;

    for (int kt = 0; kt < 512; kt += 64) {
        const int kw = (k0 + kt) >> 1;      // word base
        #pragma unroll
        for (int i = 0; i < 4; i++) {
            int f4 = af4 + 4 * i;
            uint2 v = make_uint2(0u, 0u);
            if (r0 + arow < NU) v = *(const uint2*)&g_ZuPack[(size_t)(r0 + arow) * DW + kw + f4 * 2];
            As[arow][f4 * 2]     = v.x;
            As[arow][f4 * 2 + 1] = v.y;
        }
        #pragma unroll
        for (int i = 0; i < 7; i++) {
            int idx = t + 256 * i;
            int row = idx >> 4, f4 = idx & 15;
            uint2 v = make_uint2(0u, 0u);
            if (row < WAY) v = *(const uint2*)&g_musPack[(size_t)row * DW + kw + f4 * 2];
            Bs[row][f4 * 2]     = v.x;
            Bs[row][f4 * 2 + 1] = v.y;
        }
        __syncthreads();
        #pragma unroll
        for (int ks = 0; ks < 4; ks++) {
            const int kp = ks * 8;
            uint32_t a0 = As[m0w + gid][kp + tig];
            uint32_t a1 = As[m0w + gid + 8][kp + tig];
            uint32_t a2 = As[m0w + gid][kp + tig + 4];
            uint32_t a3 = As[m0w + gid + 8][kp + tig + 4];
            #pragma unroll
            for (int nt = 0; nt < 7; nt++) {
                uint32_t b0 = Bs[n0w + nt * 8 + gid][kp + tig];
                uint32_t b1 = Bs[n0w + nt * 8 + gid][kp + tig + 4];
                mma_bf16(c[nt], a0, a1, a2, a3, b0, b1);
            }
        }
        __syncthreads();
    }
    float* out = g_Cpart + (size_t)blockIdx.y * NUW;
    #pragma unroll
    for (int nt = 0; nt < 7; nt++) {
        int j0 = n0w + nt * 8 + tig * 2;
        int gr0 = r0 + m0w + gid;
        #pragma unroll
        for (int h = 0; h < 2; h++) {
            int gr = gr0 + 8 * h;
            if (gr < NU) {
                if (j0 < WAY)     out[gr * WAY + j0]     = c[nt][2 * h];
                if (j0 + 1 < WAY) out[gr * WAY + j0 + 1] = c[nt][2 * h + 1];
            }
        }
    }
}

// K = exp(-lam*dist); wide grid (memory phase stays chip-wide — R5/R10 lesson)
__global__ void k_expK() {
    int idx = blockIdx.x * blockDim.x + threadIdx.x;
    float kv = 0.0f;
    if (idx < NUW) {
        int i = idx / WAY, j = idx - i * WAY;
        float c = 0.0f;
        #pragma unroll
        for (int s = 0; s < KSPL; s++) c += g_Cpart[s * NUW + idx];
        float d2 = g_zn2[NL + i] + g_mn2[j] - 2.0f * c;
        float dist = sqrtf(fmaxf(d2, 1e-12f));
        kv = expf(-LAMB * dist);
        g_Kmat[idx] = kv;
    }
    float bs = blockReduceSum(kv);
    if (threadIdx.x == 0) g_Kpart[blockIdx.x] = bs;
}

// ---------------- cluster-based persistent sinkhorn (NB CTAs x 512) ----------------
// One cluster.sync per iteration; err rides in the colsum exchange (slot 112).
template <int NB, int RW>
__global__ void __launch_bounds__(512, 1) k_sink(int writeF32) {
    const int t = threadIdx.x, w = t >> 5, lane = t & 31;
    const int blk = blockIdx.x;           // == cluster rank (single cluster)
    const int gw  = blk * 16 + w;
    const int rbase = gw * RW;
    __shared__ float scolW[16][128];
    __shared__ float sWerr[16];
    __shared__ float colsumBuf[2][128];
    __shared__ float sbcast[128];
    __shared__ float sErrSh;

    // Ksum from expK partials (identical fixed-order computation in every block)
    float ks = 0.0f;
    for (int i = t; i < EXPK_BLOCKS; i += 512) ks += __ldcg(&g_Kpart[i]);
    ks = blockReduceSum(ks);
    const float invKs = 1.0f / ks;

    float Kr[RW][4], a[RW], prev[RW], b[4];
    bool rv[RW], cv[4];
    int cols[4];
    #pragma unroll
    for (int c = 0; c < 4; c++) {
        int j = lane + 32 * c;
        cols[c] = j; cv[c] = (j < WAY); b[c] = cv[c] ? 1.0f : 0.0f;
    }
    #pragma unroll
    for (int k = 0; k < RW; k++) {
        int r = rbase + k;
        rv[k] = (r < NU); a[k] = 1.0f; prev[k] = 0.0f;
        #pragma unroll
        for (int c = 0; c < 4; c++)
            Kr[k][c] = (rv[k] && cv[c]) ? g_Kmat[r * WAY + cols[c]] * invKs : 0.0f;
    }

    const uint32_t colBufAddr0 = (uint32_t)__cvta_generic_to_shared(&colsumBuf[0][0]);
    const uint32_t colBufAddr1 = (uint32_t)__cvta_generic_to_shared(&colsumBuf[1][0]);

    float rowsum[RW];
    for (int it = 0; it < 1000; ++it) {
        const int p = it & 1;
        float werr = 0.0f;
        {
            float anew[RW];
            #pragma unroll
            for (int k = 0; k < RW; k++) {
                float s = 0.0f;
                #pragma unroll
                for (int c = 0; c < 4; c++) s = fmaf(Kr[k][c], b[c], s);
                #pragma unroll
                for (int off = 16; off; off >>= 1) s += __shfl_xor_sync(0xffffffffu, s, off);
                rowsum[k] = a[k] * s;
                anew[k] = rv[k] ? a[k] / rowsum[k] : 0.0f;
                if (rv[k]) werr = fmaxf(werr, fabsf(prev[k] - rowsum[k]));
            }
            #pragma unroll
            for (int c = 0; c < 4; c++) {
                float s = 0.0f;
                #pragma unroll
                for (int k = 0; k < RW; k++) s = fmaf(Kr[k][c], anew[k], s);
                scolW[w][cols[c]] = cv[c] ? s : 0.0f;
            }
        }   // anew dead before the cluster barrier (register pressure)
        if (lane == 0) sWerr[w] = werr;
        __syncthreads();
        if (t < 128) {
            float s;
            if (t == ERRSLOT) {
                s = sWerr[0];
                #pragma unroll
                for (int ww = 1; ww < 16; ww++) s = fmaxf(s, sWerr[ww]);
            } else {
                s = scolW[0][t];
                #pragma unroll
                for (int ww = 1; ww < 16; ww++) s += scolW[ww][t];
            }
            colsumBuf[p][t] = s;        // published by arrive.release below
        }
        CLUSTER_SYNC();
        {
            const uint32_t base = (p ? colBufAddr1 : colBufAddr0);
            if (t < 100) {
                float s = 0.0f;
                #pragma unroll
                for (int bb = 0; bb < NB; bb++) s += dsmem_ld(base + t * 4, (uint32_t)bb);
                sbcast[t] = s;
            } else if (t == ERRSLOT) {
                float e = 0.0f;
                #pragma unroll
                for (int bb = 0; bb < NB; bb++) e = fmaxf(e, dsmem_ld(base + ERRSLOT * 4, (uint32_t)bb));
                sErrSh = e;
            }
        }
        __syncthreads();
        if (sErrSh <= 1e-6f) break;     // a,b stay pre-update: exact reference semantics
        #pragma unroll
        for (int k = 0; k < RW; k++) {
            if (rv[k]) { a[k] = a[k] / rowsum[k]; prev[k] = rowsum[k]; }
        }
        #pragma unroll
        for (int c = 0; c < 4; c++) if (cv[c]) b[c] = 15.0f / sbcast[cols[c]];
        // no trailing sync needed: next-iter scolW writes precede its own
        // __syncthreads; next-iter sbcast writes follow the next CLUSTER_SYNC.
    }

    // epilogue: write packed Pu pairs (+ f32 on final epoch) + colP partials
    float colacc[4] = {0.f, 0.f, 0.f, 0.f};
    #pragma unroll
    for (int k = 0; k < RW; k += 2) {   // rv[k]==rv[k+1] (NU even, rbase even)
        int r = rbase + k;
        if (!rv[k]) continue;
        #pragma unroll
        for (int c = 0; c < 4; c++) {
            if (cv[c]) {
                float p0 = a[k] * Kr[k][c] * b[c];
                float p1 = a[k + 1] * Kr[k + 1][c] * b[c];
                g_PuPack[(r >> 1) * WAY + cols[c]] = bfpack(p0, p1);
                if (writeF32) {
                    g_Pu[r * WAY + cols[c]]       = p0;
                    g_Pu[(r + 1) * WAY + cols[c]] = p1;
                }
                colacc[c] += p0 + p1;
            }
        }
    }
    __syncthreads();
    #pragma unroll
    for (int c = 0; c < 4; c++) scolW[w][cols[c]] = cv[c] ? colacc[c] : 0.0f;
    __syncthreads();
    if (t < 128) {
        float s = scolW[0][t];
        #pragma unroll
        for (int ww = 1; ww < 16; ww++) s += scolW[ww][t];
        __stcg(&g_colPpart[blk * 128 + t], s);
    }
    CLUSTER_SYNC();                     // no CTA exits while peers may still read its smem
}

// ===== bf16 tensor-core epilogue GEMM from pre-packed operands
__global__ void __launch_bounds__(256) k_epi() {
    const int n0 = blockIdx.x * 64;
    const int u0 = blockIdx.y * USPL;
    const int t  = threadIdx.x;
    const int w  = t >> 5, lane = t & 31;
    const int gid = lane >> 2, tig = lane & 3;
    const int m0w = w * 16;

    __shared__ uint32_t As[128][20];  // [class][u-pair] bf16x2
    __shared__ uint32_t Bs[64][20];   // [dim][u-pair]

    float c[8][4];
    #pragma unroll
    for (int i = 0; i < 8; i++)
        #pragma unroll
        for (int jj = 0; jj < 4; jj++) c[i][jj] = 0.0f;

    const int am  = t & 127;
    const int ah  = t >> 7;
    const int bup = t >> 4;
    const int bnn = (t & 15) * 4;

    for (int kt = 0; kt < 12; kt++) {
        const int ub = kt * 32;
        const int pairBase = (u0 >> 1) + (ub >> 1);
        #pragma unroll
        for (int i = 0; i < 8; i++) {
            int kp = ah * 8 + i;
            int ul = ub + kp * 2;
            uint32_t v = 0u;
            if (am < WAY && ul < USPL && u0 + ul < NU)
                v = g_PuPack[(pairBase + kp) * WAY + am];
            As[am][kp] = v;
        }
        {
            int ul = ub + bup * 2;
            uint2 w0 = make_uint2(0u, 0u), w1 = make_uint2(0u, 0u);
            if (ul < USPL && u0 + ul < NU) {
                w0 = *(const uint2*)&g_ZuPack[(size_t)(u0 + ul) * DW + ((n0 + bnn) >> 1)];
                w1 = *(const uint2*)&g_ZuPack[(size_t)(u0 + ul + 1) * DW + ((n0 + bnn) >> 1)];
            }
            Bs[bnn + 0][bup] = prmt(w0.x, w1.x, 0x5410);
            Bs[bnn + 1][bup] = prmt(w0.x, w1.x, 0x7632);
            Bs[bnn + 2][bup] = prmt(w0.y, w1.y, 0x5410);
            Bs[bnn + 3][bup] = prmt(w0.y, w1.y, 0x7632);
        }
        __syncthreads();
        #pragma unroll
        for (int ks = 0; ks < 2; ks++) {
            const int kp = ks * 8;
            uint32_t a0 = As[m0w + gid][kp + tig];
            uint32_t a1 = As[m0w + gid + 8][kp + tig];
            uint32_t a2 = As[m0w + gid][kp + tig + 4];
            uint32_t a3 = As[m0w + gid + 8][kp + tig + 4];
            #pragma unroll
            for (int nt = 0; nt < 8; nt++) {
                uint32_t b0 = Bs[nt * 8 + gid][kp + tig];
                uint32_t b1 = Bs[nt * 8 + gid][kp + tig + 4];
                mma_bf16(c[nt], a0, a1, a2, a3, b0, b1);
            }
        }
        __syncthreads();
    }
    float* outp = g_Epart + (size_t)blockIdx.y * WAYD;
    #pragma unroll
    for (int nt = 0; nt < 8; nt++) {
        int dcol = n0 + nt * 8 + tig * 2;
        #pragma unroll
        for (int h = 0; h < 2; h++) {
            int j = m0w + gid + 8 * h;
            if (j < WAY) {
                outp[(size_t)j * D + dcol]     = c[nt][2 * h];
                outp[(size_t)j * D + dcol + 1] = c[nt][2 * h + 1];
            }
        }
    }
}

// one block per class: mus update + musPack + mn2 for next epoch
__global__ void __launch_bounds__(512) k_update(int nb) {
    const int j = blockIdx.x, t = threadIdx.x;
    __shared__ float sden;
    if (t == 0) {
        float s = 0.0f;
        for (int bb = 0; bb < nb; bb++) s += g_colPpart[bb * 128 + j];
        sden = 5.0f + s;
    }
    __syncthreads();
    const float invden = 1.0f / sden;
    float ss = 0.0f;
    #pragma unroll
    for (int q = 0; q < 4; q++) {
        int i = t + 512 * q;           // word index 0..2047
        int idx = j * D + 2 * i;
        float E0 = 0.0f, E1 = 0.0f;
        #pragma unroll
        for (int s = 0; s < 4; s++) {
            E0 += g_Epart[s * WAYD + idx];
            E1 += g_Epart[s * WAYD + idx + 1];
        }
        float em0 = (g_Sl[idx] + E0) * invden;
        float em1 = (g_Sl[idx + 1] + E1) * invden;
        float m0 = g_mus[idx],     m1 = g_mus[idx + 1];
        m0 = m0 + ALPHAC * (em0 - m0);
        m1 = m1 + ALPHAC * (em1 - m1);
        g_mus[idx] = m0; g_mus[idx + 1] = m1;
        g_musPack[j * DW + i] = bfpack(m0, m1);
        ss += m0 * m0 + m1 * m1;
    }
    ss = blockReduceSum(ss);
    if (t == 0) g_mn2[j] = ss;
}

// ---------------- output: fused logP + accuracy (one block per row) ----------------
__global__ void __launch_bounds__(128) k_outacc(float* __restrict__ out,
                                               const int* __restrict__ labels) {
    const int i = blockIdx.x, t = threadIdx.x;
    __shared__ float sv[128];
    __shared__ int   sj[128];
    float p = 0.0f;
    if (t < WAY) {
        p = g_Pu[i * WAY + t];
        out[i * WAY + t] = logf(p + 1e-5f);
    }
    sv[t] = (t < WAY) ? p : -1.0f;
    sj[t] = t;
    __syncthreads();
    #pragma unroll
    for (int off = 64; off; off >>= 1) {
        if (t < off) {
            float vo = sv[t + off]; int jo = sj[t + off];
            if (vo > sv[t] || (vo == sv[t] && jo < sj[t])) { sv[t] = vo; sj[t] = jo; }
        }
        __syncthreads();
    }
    if (t == 0 && sj[0] == labels[NL + i]) atomicAdd(&g_accN, 1);
}

__global__ void k_accw(float* __restrict__ out) {
    out[NUW] = (float)g_accN * (1.0f / NU);
}

// ---------------- launch ----------------
extern "C" void kernel_launch(void* const* d_in, const int* in_sizes, int n_in,
                              void* d_out, int out_size) {
    const float* X = (const float*)d_in[0];
    const int* labels = (const int*)d_in[1];
    float* out = (float*)d_out;

    // probe 16-CTA nonportable cluster support (host API, deterministic per machine)
    int nb = 8;
    {
        cudaFuncSetAttribute((const void*)k_sink<16, 6>,
                             cudaFuncAttributeNonPortableClusterSizeAllowed, 1);
        cudaLaunchConfig_t pc = {};
        pc.gridDim = dim3(16, 1, 1);
        pc.blockDim = dim3(512, 1, 1);
        int cs = 0;
        cudaError_t err = cudaOccupancyMaxPotentialClusterSize(
            &cs, (const void*)k_sink<16, 6>, &pc);
        if (err == cudaSuccess && cs >= 16) nb = 16;
        else cudaGetLastError();
    }

    k_pre1<<<NTOT, 256>>>(X);
    k_colmeans<<<D / 64, 256>>>();
    k_pre2<<<NTOT, 256>>>();
    k_Sl<<<WAY, 512>>>();

    cudaLaunchConfig_t cfg = {};
    cudaLaunchAttribute attrs[1];
    attrs[0].id = cudaLaunchAttributeClusterDimension;
    attrs[0].val.clusterDim.x = nb;
    attrs[0].val.clusterDim.y = 1;
    attrs[0].val.clusterDim.z = 1;
    cfg.gridDim = dim3(nb, 1, 1);
    cfg.blockDim = dim3(512, 1, 1);
    cfg.attrs = attrs;
    cfg.numAttrs = 1;

    for (int e = 0; e < 21; e++) {
        k_gram<<<dim3(24, KSPL), 256>>>();
        k_expK<<<EXPK_BLOCKS, 256>>>();
        int wf = (e == 20) ? 1 : 0;
        if (nb == 16) cudaLaunchKernelEx(&cfg, k_sink<16, 6>, wf);
        else          cudaLaunchKernelEx(&cfg, k_sink<8, 12>, wf);
        if (e < 20) {
            k_epi<<<dim3(64, 4), 256>>>();
            k_update<<<WAY, 512>>>(nb);
        }
    }
    k_outacc<<<NU, 128>>>(out, labels);
    if (out_size > NUW) k_accw<<<1, 1>>>(out);
}